// round 1
// baseline (speedup 1.0000x reference)
#include <cuda_runtime.h>
#include <cuda_bf16.h>
#include <mma.h>

using namespace nvcuda;

#define BB   8
#define NN   2000
#define CC   4096
#define HID  42
#define NCLS 20
#define NWRD 64          // 64 * 32 = 2048 bits >= 2000
#define F2   84          // 2*HID
#define THRESHF 0.5f
#define EPSF 1e-12f

// ---------------- scratch (device globals: allocation-free) ----------------
__device__ __nv_bfloat16 g_xb[(size_t)BB * NN * CC];     // bf16 copy of x1
__device__ float    g_inv_s[BB * NN];                    // 1/rowsum (0 if sum==0)
__device__ float    g_norm[BB * NN];                     // max(||x_i||, EPS)
__device__ unsigned g_Aadj[(size_t)BB * NN * NWRD];      // IoU adjacency bitmask
__device__ unsigned g_Asim[(size_t)BB * NN * NWRD];      // cosine-sim adjacency bitmask
__device__ float    g_Z[(size_t)BB * NN * F2];           // x @ [W_cls1 | W_det1]
__device__ float    g_H[(size_t)BB * NN * F2];           // relu(A @ (Z/s) + b1)
__device__ float    g_T[(size_t)BB * NN * 40];           // H @ [W_cls2 | W_det2]

// ---------------- 1) row stats + bf16 convert ----------------
__global__ void prep_kernel(const float* __restrict__ x) {
    int row = blockIdx.x;                               // 0..BB*NN-1
    const float4* p = (const float4*)(x + (size_t)row * CC);
    __nv_bfloat162* q = (__nv_bfloat162*)(g_xb + (size_t)row * CC);
    int t = threadIdx.x;                                // 128 threads
    float s = 0.f, sq = 0.f;
#pragma unroll
    for (int it = 0; it < (CC / 4) / 128; ++it) {
        int i4 = t + it * 128;
        float4 v = p[i4];
        s  += v.x + v.y + v.z + v.w;
        sq += v.x * v.x + v.y * v.y + v.z * v.z + v.w * v.w;
        q[i4 * 2]     = __floats2bfloat162_rn(v.x, v.y);
        q[i4 * 2 + 1] = __floats2bfloat162_rn(v.z, v.w);
    }
    __shared__ float ss[128], sqq[128];
    ss[t] = s; sqq[t] = sq;
    __syncthreads();
    for (int off = 64; off > 0; off >>= 1) {
        if (t < off) { ss[t] += ss[t + off]; sqq[t] += sqq[t + off]; }
        __syncthreads();
    }
    if (t == 0) {
        float sum = ss[0];
        g_inv_s[row] = (sum == 0.f) ? 0.f : (1.f / sum);
        g_norm[row]  = fmaxf(sqrtf(sqq[0]), EPSF);
    }
}

// ---------------- 2) pairwise IoU -> A_adj bitmask ----------------
__global__ void iou_kernel(const float* __restrict__ boxes) {
    int b = blockIdx.y;
    __shared__ float4 bx[NN];
    int t = threadIdx.x;                                // 256
    const float4* src = (const float4*)boxes + (size_t)b * NN;
    for (int idx = t; idx < NN; idx += 256) bx[idx] = src[idx];
    __syncthreads();

    int i = blockIdx.x * 4 + (t >> 6);                  // 4 rows / block, i < 2000
    int w = t & 63;                                     // word index
    float4 bi = bx[i];
    float ai = __fmul_rn(__fsub_rn(bi.z, bi.x), __fsub_rn(bi.w, bi.y));
    unsigned word = 0;
#pragma unroll 4
    for (int k = 0; k < 32; ++k) {
        int j = w * 32 + k;
        if (j < NN) {
            float4 bj = bx[j];
            float aj  = __fmul_rn(__fsub_rn(bj.z, bj.x), __fsub_rn(bj.w, bj.y));
            float ltx = fmaxf(bi.x, bj.x), lty = fmaxf(bi.y, bj.y);
            float rbx = fminf(bi.z, bj.z), rby = fminf(bi.w, bj.w);
            float wx  = fmaxf(__fsub_rn(rbx, ltx), 0.f);
            float wy  = fmaxf(__fsub_rn(rby, lty), 0.f);
            float inter = __fmul_rn(wx, wy);
            float uni   = __fsub_rn(__fadd_rn(ai, aj), inter);
            float iou   = inter / fmaxf(uni, EPSF);
            if (iou >= THRESHF) word |= (1u << k);
        }
    }
    g_Aadj[((size_t)b * NN + i) * NWRD + w] = word;
}

// ---------------- 3) G = x x^T (bf16 WMMA), threshold -> A_sim bitmask ----------------
#define SBM 128
#define SBN 128
#define SBK 32
#define SLD (SBK + 8)

__global__ __launch_bounds__(256) void sim_kernel() {
    __shared__ __align__(32) __nv_bfloat16 As[SBM][SLD];
    __shared__ __align__(32) __nv_bfloat16 Bs[SBN][SLD];
    __shared__ __align__(32) float stage[8][16][40];

    int b  = blockIdx.z;
    int i0 = blockIdx.y * SBM;
    int j0 = blockIdx.x * SBN;
    int tid = threadIdx.x;
    int wid = tid >> 5, lane = tid & 31;
    int wr = wid >> 2, wc = wid & 3;                    // warp 64x32 tile

    wmma::fragment<wmma::accumulator, 16, 16, 16, float> acc[4][2];
#pragma unroll
    for (int i = 0; i < 4; ++i)
#pragma unroll
        for (int j = 0; j < 2; ++j) wmma::fill_fragment(acc[i][j], 0.f);

    const __nv_bfloat16* xb = g_xb + (size_t)b * NN * CC;
    int r  = tid >> 1;
    int sg = (tid & 1) * 16;

    for (int k0 = 0; k0 < CC; k0 += SBK) {
        // A rows i0..i0+127
        {
            uint4 v0 = make_uint4(0, 0, 0, 0), v1 = make_uint4(0, 0, 0, 0);
            if (i0 + r < NN) {
                const __nv_bfloat16* s = xb + (size_t)(i0 + r) * CC + k0 + sg;
                v0 = *(const uint4*)s; v1 = *(const uint4*)(s + 8);
            }
            *(uint4*)&As[r][sg]     = v0;
            *(uint4*)&As[r][sg + 8] = v1;
        }
        // B rows j0..j0+127
        {
            uint4 v0 = make_uint4(0, 0, 0, 0), v1 = make_uint4(0, 0, 0, 0);
            if (j0 + r < NN) {
                const __nv_bfloat16* s = xb + (size_t)(j0 + r) * CC + k0 + sg;
                v0 = *(const uint4*)s; v1 = *(const uint4*)(s + 8);
            }
            *(uint4*)&Bs[r][sg]     = v0;
            *(uint4*)&Bs[r][sg + 8] = v1;
        }
        __syncthreads();
#pragma unroll
        for (int kf = 0; kf < SBK / 16; ++kf) {
            wmma::fragment<wmma::matrix_a, 16, 16, 16, __nv_bfloat16, wmma::row_major> af[4];
            wmma::fragment<wmma::matrix_b, 16, 16, 16, __nv_bfloat16, wmma::col_major> bf[2];
#pragma unroll
            for (int i = 0; i < 4; ++i)
                wmma::load_matrix_sync(af[i], &As[wr * 64 + i * 16][kf * 16], SLD);
#pragma unroll
            for (int j = 0; j < 2; ++j)
                wmma::load_matrix_sync(bf[j], &Bs[wc * 32 + j * 16][kf * 16], SLD);
#pragma unroll
            for (int i = 0; i < 4; ++i)
#pragma unroll
                for (int j = 0; j < 2; ++j)
                    wmma::mma_sync(acc[i][j], af[i], bf[j], acc[i][j]);
        }
        __syncthreads();
    }

    // epilogue: threshold G >= 0.5 * n_i * n_j, build bit words (warp cols = 1 word)
    int coln = j0 + wc * 32 + lane;
    bool colok = coln < NN;
    float nj = colok ? g_norm[b * NN + coln] : 0.f;
    int word_idx = (j0 + wc * 32) >> 5;
#pragma unroll
    for (int fi = 0; fi < 4; ++fi) {
        wmma::store_matrix_sync(&stage[wid][0][0],  acc[fi][0], 40, wmma::mem_row_major);
        wmma::store_matrix_sync(&stage[wid][0][16], acc[fi][1], 40, wmma::mem_row_major);
        __syncwarp();
        int rowbase = i0 + wr * 64 + fi * 16;
        for (int rr = 0; rr < 16; ++rr) {
            int row = rowbase + rr;
            if (row >= NN) break;                       // uniform across warp
            float ni  = g_norm[b * NN + row];
            float val = stage[wid][rr][lane];
            bool pred = colok && (val >= 0.5f * ni * nj);
            unsigned wbits = __ballot_sync(0xFFFFFFFFu, pred);
            if (lane == 0) g_Asim[((size_t)b * NN + row) * NWRD + word_idx] = wbits;
        }
        __syncwarp();
    }
}

// ---------------- 4) Z = x @ [W_cls1 | W_det1]   (fp32, 4x4 register tile) ----------------
#define ZBM 64
#define ZBK 32
__global__ __launch_bounds__(336) void z_kernel(const float* __restrict__ x,
                                                const float* __restrict__ Wc,
                                                const float* __restrict__ Wd) {
    __shared__ float Xs[ZBK][ZBM];      // [k][row]
    __shared__ float Ws[ZBK][88];       // [k][col], padded
    int b  = blockIdx.y;
    int i0 = blockIdx.x * ZBM;
    int t  = threadIdx.x;               // 336 = 21 col-threads x 16 row-threads
    int colt = t % 21, rowt = t / 21;
    int c0 = colt * 4, r0 = rowt * 4;
    float acc[4][4] = {};
    const float* xb = x + (size_t)b * NN * CC;

    for (int k0 = 0; k0 < CC; k0 += ZBK) {
        for (int idx = t; idx < ZBM * ZBK; idx += 336) {
            int rr = idx / ZBK, kk = idx % ZBK;
            Xs[kk][rr] = (i0 + rr < NN) ? xb[(size_t)(i0 + rr) * CC + k0 + kk] : 0.f;
        }
        for (int idx = t; idx < ZBK * F2; idx += 336) {
            int kk = idx / F2, c = idx % F2;
            Ws[kk][c] = (c < HID) ? Wc[(size_t)(k0 + kk) * HID + c]
                                  : Wd[(size_t)(k0 + kk) * HID + (c - HID)];
        }
        __syncthreads();
#pragma unroll
        for (int kk = 0; kk < ZBK; ++kk) {
            float4 xv = *(const float4*)&Xs[kk][r0];
            float4 wv = *(const float4*)&Ws[kk][c0];
            acc[0][0] += xv.x * wv.x; acc[0][1] += xv.x * wv.y; acc[0][2] += xv.x * wv.z; acc[0][3] += xv.x * wv.w;
            acc[1][0] += xv.y * wv.x; acc[1][1] += xv.y * wv.y; acc[1][2] += xv.y * wv.z; acc[1][3] += xv.y * wv.w;
            acc[2][0] += xv.z * wv.x; acc[2][1] += xv.z * wv.y; acc[2][2] += xv.z * wv.z; acc[2][3] += xv.z * wv.w;
            acc[3][0] += xv.w * wv.x; acc[3][1] += xv.w * wv.y; acc[3][2] += xv.w * wv.z; acc[3][3] += xv.w * wv.w;
        }
        __syncthreads();
    }
#pragma unroll
    for (int rr = 0; rr < 4; ++rr) {
        int row = i0 + r0 + rr;
        if (row < NN) {
#pragma unroll
            for (int cc = 0; cc < 4; ++cc)
                g_Z[((size_t)b * NN + row) * F2 + c0 + cc] = acc[rr][cc];
        }
    }
}

// ---------------- 5) H = relu(A @ (Z/s) + b1) ----------------
__global__ void agg1_kernel(const float* __restrict__ b1c, const float* __restrict__ b1d) {
    int i = blockIdx.x, br = blockIdx.y, b = blockIdx.z;
    __shared__ unsigned wds[NWRD];
    int t = threadIdx.x;                                 // 64
    const unsigned* A = (br ? g_Asim : g_Aadj) + ((size_t)b * NN + i) * NWRD;
    if (t < NWRD) wds[t] = A[t];
    __syncthreads();
    if (t >= HID) return;
    float acc = 0.f;
    const float* Zb  = g_Z + (size_t)b * NN * F2 + br * HID;
    const float* ivs = g_inv_s + b * NN;
    for (int w = 0; w < NWRD; ++w) {
        unsigned m = wds[w];
        while (m) {
            int j = w * 32 + __ffs(m) - 1;
            m &= m - 1;
            acc += Zb[(size_t)j * F2 + t] * ivs[j];
        }
    }
    float bias = br ? b1d[t] : b1c[t];
    g_H[((size_t)b * NN + i) * F2 + br * HID + t] = fmaxf(acc + bias, 0.f);
}

// ---------------- 6) T = H @ [W_cls2 | W_det2] ----------------
__global__ void t_kernel(const float* __restrict__ W2c, const float* __restrict__ W2d) {
    int g = blockIdx.x * blockDim.x + threadIdx.x;
    if (g >= BB * NN * 40) return;
    int c40 = g % 40; int i = g / 40;
    int br = c40 / 20, c = c40 % 20;
    const float* W = br ? W2d : W2c;
    const float* h = g_H + (size_t)i * F2 + br * HID;
    float acc = 0.f;
#pragma unroll
    for (int f = 0; f < HID; ++f) acc += h[f] * W[f * NCLS + c];
    g_T[(size_t)i * 40 + c40] = acc;
}

// ---------------- 7) out_pre = A @ T + b2 ----------------
__global__ void agg2_kernel(const float* __restrict__ b2c, const float* __restrict__ b2d,
                            float* __restrict__ out) {
    int i = blockIdx.x, br = blockIdx.y, b = blockIdx.z;
    __shared__ unsigned wds[NWRD];
    int t = threadIdx.x;                                 // 32
    const unsigned* A = (br ? g_Asim : g_Aadj) + ((size_t)b * NN + i) * NWRD;
    wds[t] = A[t]; wds[t + 32] = A[t + 32];
    __syncthreads();
    if (t >= NCLS) return;
    float acc = 0.f;
    const float* Tb = g_T + (size_t)b * NN * 40 + br * NCLS;
    for (int w = 0; w < NWRD; ++w) {
        unsigned m = wds[w];
        while (m) {
            int j = w * 32 + __ffs(m) - 1;
            m &= m - 1;
            acc += Tb[(size_t)j * 40 + t];
        }
    }
    acc += br ? b2d[t] : b2c[t];
    out[(size_t)br * BB * NN * NCLS + ((size_t)b * NN + i) * NCLS + t] = acc;
}

// ---------------- 8) softmax over classes (cls half) ----------------
__global__ void softmax_cls(float* __restrict__ out) {
    int rrow = blockIdx.x * blockDim.x + threadIdx.x;
    if (rrow >= BB * NN) return;
    float* p = out + (size_t)rrow * NCLS;
    float mx = -1e30f;
#pragma unroll
    for (int c = 0; c < NCLS; ++c) mx = fmaxf(mx, p[c]);
    float e[NCLS]; float s = 0.f;
#pragma unroll
    for (int c = 0; c < NCLS; ++c) { e[c] = expf(p[c] - mx); s += e[c]; }
    float inv = 1.f / s;
#pragma unroll
    for (int c = 0; c < NCLS; ++c) p[c] = e[c] * inv;
}

// ---------------- 9) softmax over proposals (det half, per (b, class)) ----------------
__global__ void softmax_det(float* __restrict__ out) {
    int b = blockIdx.x / NCLS, c = blockIdx.x % NCLS;
    float* p = out + (size_t)BB * NN * NCLS + (size_t)b * NN * NCLS + c;
    __shared__ float buf[NN];
    __shared__ float red[256];
    int t = threadIdx.x;
    float mx = -1e30f;
    for (int j = t; j < NN; j += 256) {
        float v = p[(size_t)j * NCLS];
        buf[j] = v;
        mx = fmaxf(mx, v);
    }
    red[t] = mx; __syncthreads();
    for (int off = 128; off > 0; off >>= 1) {
        if (t < off) red[t] = fmaxf(red[t], red[t + off]);
        __syncthreads();
    }
    mx = red[0];
    __syncthreads();
    float s = 0.f;
    for (int j = t; j < NN; j += 256) {
        float e = expf(buf[j] - mx);
        buf[j] = e;
        s += e;
    }
    red[t] = s; __syncthreads();
    for (int off = 128; off > 0; off >>= 1) {
        if (t < off) red[t] += red[t + off];
        __syncthreads();
    }
    float inv = 1.f / red[0];
    for (int j = t; j < NN; j += 256) p[(size_t)j * NCLS] = buf[j] * inv;
}

// ---------------- launcher ----------------
extern "C" void kernel_launch(void* const* d_in, const int* in_sizes, int n_in,
                              void* d_out, int out_size) {
    const float* x1    = (const float*)d_in[0];
    // d_in[1] = x2 (unused by reference after pooling)
    const float* boxes = (const float*)d_in[2];
    const float* Wc1   = (const float*)d_in[3];
    const float* bc1   = (const float*)d_in[4];
    const float* Wc2   = (const float*)d_in[5];
    const float* bc2   = (const float*)d_in[6];
    const float* Wd1   = (const float*)d_in[7];
    const float* bd1   = (const float*)d_in[8];
    const float* Wd2   = (const float*)d_in[9];
    const float* bd2   = (const float*)d_in[10];
    float* out = (float*)d_out;

    prep_kernel<<<BB * NN, 128>>>(x1);
    iou_kernel<<<dim3(NN / 4, BB), 256>>>(boxes);
    sim_kernel<<<dim3((NN + SBN - 1) / SBN, (NN + SBM - 1) / SBM, BB), 256>>>();
    z_kernel<<<dim3((NN + ZBM - 1) / ZBM, BB), 336>>>(x1, Wc1, Wd1);
    agg1_kernel<<<dim3(NN, 2, BB), 64>>>(bc1, bd1);
    t_kernel<<<(BB * NN * 40 + 255) / 256, 256>>>(Wc2, Wd2);
    agg2_kernel<<<dim3(NN, 2, BB), 32>>>(bc2, bd2, out);
    softmax_cls<<<(BB * NN + 255) / 256, 256>>>(out);
    softmax_det<<<BB * NCLS, 256>>>(out);
}

// round 2
// speedup vs baseline: 1.7999x; 1.7999x over previous
#include <cuda_runtime.h>
#include <cuda_bf16.h>
#include <mma.h>

using namespace nvcuda;

#define BB   8
#define NN   2000
#define CC   4096
#define HID  42
#define NCLS 20
#define NWRD 64          // 64 * 32 = 2048 bits >= 2000
#define F2   84          // 2*HID
#define THRESHF 0.5f
#define EPSF 1e-12f

// ---------------- scratch (device globals: allocation-free) ----------------
__device__ __nv_bfloat16 g_xb[(size_t)BB * NN * CC];     // bf16 hi of x1
__device__ __nv_bfloat16 g_xl[(size_t)BB * NN * CC];     // bf16 lo residual of x1
__device__ float    g_inv_s[BB * NN];                    // 1/rowsum (0 if sum==0)
__device__ float    g_norm[BB * NN];                     // max(||x_i||, EPS)
__device__ unsigned g_Aadj[(size_t)BB * NN * NWRD];      // IoU adjacency bitmask
__device__ unsigned g_Asim[(size_t)BB * NN * NWRD];      // cosine-sim adjacency bitmask
__device__ float    g_Z[(size_t)BB * NN * F2];           // (x @ [W_cls1|W_det1]) * inv_s
__device__ float    g_H[(size_t)BB * NN * F2];           // relu(A @ Z + b1)
__device__ float    g_T[(size_t)BB * NN * 40];           // H @ [W_cls2 | W_det2]
__device__ __nv_bfloat16 g_Wh[4096 * 96];                // [W_cls1|W_det1|0pad] hi
__device__ __nv_bfloat16 g_Wl[4096 * 96];                // lo

// ---------------- 1) row stats + bf16 hi/lo convert ----------------
__global__ void prep_kernel(const float* __restrict__ x) {
    int row = blockIdx.x;                               // 0..BB*NN-1
    const float4* p = (const float4*)(x + (size_t)row * CC);
    __nv_bfloat162* q  = (__nv_bfloat162*)(g_xb + (size_t)row * CC);
    __nv_bfloat162* ql = (__nv_bfloat162*)(g_xl + (size_t)row * CC);
    int t = threadIdx.x;                                // 128 threads
    float s = 0.f, sq = 0.f;
#pragma unroll
    for (int it = 0; it < (CC / 4) / 128; ++it) {
        int i4 = t + it * 128;
        float4 v = p[i4];
        s  += v.x + v.y + v.z + v.w;
        sq += v.x * v.x + v.y * v.y + v.z * v.z + v.w * v.w;
        __nv_bfloat162 h0 = __floats2bfloat162_rn(v.x, v.y);
        __nv_bfloat162 h1 = __floats2bfloat162_rn(v.z, v.w);
        q[i4 * 2]     = h0;
        q[i4 * 2 + 1] = h1;
        __nv_bfloat162 l0 = __floats2bfloat162_rn(v.x - __bfloat162float(h0.x),
                                                  v.y - __bfloat162float(h0.y));
        __nv_bfloat162 l1 = __floats2bfloat162_rn(v.z - __bfloat162float(h1.x),
                                                  v.w - __bfloat162float(h1.y));
        ql[i4 * 2]     = l0;
        ql[i4 * 2 + 1] = l1;
    }
    __shared__ float ss[128], sqq[128];
    ss[t] = s; sqq[t] = sq;
    __syncthreads();
    for (int off = 64; off > 0; off >>= 1) {
        if (t < off) { ss[t] += ss[t + off]; sqq[t] += sqq[t + off]; }
        __syncthreads();
    }
    if (t == 0) {
        float sum = ss[0];
        g_inv_s[row] = (sum == 0.f) ? 0.f : (1.f / sum);
        g_norm[row]  = fmaxf(sqrtf(sqq[0]), EPSF);
    }
}

// ---------------- 1b) weight hi/lo prep ----------------
__global__ void wprep_kernel(const float* __restrict__ Wc, const float* __restrict__ Wd) {
    int idx = blockIdx.x * blockDim.x + threadIdx.x;    // 4096*96
    if (idx >= 4096 * 96) return;
    int k = idx / 96, c = idx % 96;
    float v = 0.f;
    if (c < HID)      v = Wc[k * HID + c];
    else if (c < F2)  v = Wd[k * HID + c - HID];
    __nv_bfloat16 h = __float2bfloat16(v);
    g_Wh[idx] = h;
    g_Wl[idx] = __float2bfloat16(v - __bfloat162float(h));
}

// ---------------- 2) pairwise IoU -> A_adj bitmask ----------------
__global__ void iou_kernel(const float* __restrict__ boxes) {
    int b = blockIdx.y;
    __shared__ float4 bx[NN];
    int t = threadIdx.x;                                // 256
    const float4* src = (const float4*)boxes + (size_t)b * NN;
    for (int idx = t; idx < NN; idx += 256) bx[idx] = src[idx];
    __syncthreads();

    int i = blockIdx.x * 4 + (t >> 6);                  // 4 rows / block
    int w = t & 63;                                     // word index
    float4 bi = bx[i];
    float ai = __fmul_rn(__fsub_rn(bi.z, bi.x), __fsub_rn(bi.w, bi.y));
    unsigned word = 0;
#pragma unroll 4
    for (int k = 0; k < 32; ++k) {
        int j = w * 32 + k;
        if (j < NN) {
            float4 bj = bx[j];
            float aj  = __fmul_rn(__fsub_rn(bj.z, bj.x), __fsub_rn(bj.w, bj.y));
            float ltx = fmaxf(bi.x, bj.x), lty = fmaxf(bi.y, bj.y);
            float rbx = fminf(bi.z, bj.z), rby = fminf(bi.w, bj.w);
            float wx  = fmaxf(__fsub_rn(rbx, ltx), 0.f);
            float wy  = fmaxf(__fsub_rn(rby, lty), 0.f);
            float inter = __fmul_rn(wx, wy);
            float uni   = __fsub_rn(__fadd_rn(ai, aj), inter);
            float iou   = inter / fmaxf(uni, EPSF);
            if (iou >= THRESHF) word |= (1u << k);
        }
    }
    g_Aadj[((size_t)b * NN + i) * NWRD + w] = word;
}

// ---------------- 3) G = x x^T (bf16 WMMA, upper-tri blocks), threshold -> A_sim ----------------
#define SBM 128
#define SBN 128
#define SBK 32
#define SLD (SBK + 8)
#define NTIL 16          // ceil(2000/128)

__global__ __launch_bounds__(256) void sim_kernel() {
    __shared__ __align__(32) __nv_bfloat16 As[SBM][SLD];
    __shared__ __align__(32) __nv_bfloat16 Bs[SBN][SLD];
    __shared__ __align__(32) float stage[8][16][40];
    __shared__ unsigned wbits_s[8][64];

    int b  = blockIdx.z;
    // triangular tile decode: blocks cover (ti, tj) with tj >= ti
    int tt = blockIdx.x;
    int ti = 0, rem = tt;
    while (rem >= (NTIL - ti)) { rem -= (NTIL - ti); ++ti; }
    int tj = ti + rem;
    int i0 = ti * SBM;
    int j0 = tj * SBN;

    int tid = threadIdx.x;
    int wid = tid >> 5, lane = tid & 31;
    int wr = wid >> 2, wc = wid & 3;                    // warp 64x32 tile

    wmma::fragment<wmma::accumulator, 16, 16, 16, float> acc[4][2];
#pragma unroll
    for (int i = 0; i < 4; ++i)
#pragma unroll
        for (int j = 0; j < 2; ++j) wmma::fill_fragment(acc[i][j], 0.f);

    const __nv_bfloat16* xb = g_xb + (size_t)b * NN * CC;
    int r  = tid >> 1;
    int sg = (tid & 1) * 16;

    for (int k0 = 0; k0 < CC; k0 += SBK) {
        {
            uint4 v0 = make_uint4(0, 0, 0, 0), v1 = make_uint4(0, 0, 0, 0);
            if (i0 + r < NN) {
                const __nv_bfloat16* s = xb + (size_t)(i0 + r) * CC + k0 + sg;
                v0 = *(const uint4*)s; v1 = *(const uint4*)(s + 8);
            }
            *(uint4*)&As[r][sg]     = v0;
            *(uint4*)&As[r][sg + 8] = v1;
        }
        {
            uint4 v0 = make_uint4(0, 0, 0, 0), v1 = make_uint4(0, 0, 0, 0);
            if (j0 + r < NN) {
                const __nv_bfloat16* s = xb + (size_t)(j0 + r) * CC + k0 + sg;
                v0 = *(const uint4*)s; v1 = *(const uint4*)(s + 8);
            }
            *(uint4*)&Bs[r][sg]     = v0;
            *(uint4*)&Bs[r][sg + 8] = v1;
        }
        __syncthreads();
#pragma unroll
        for (int kf = 0; kf < SBK / 16; ++kf) {
            wmma::fragment<wmma::matrix_a, 16, 16, 16, __nv_bfloat16, wmma::row_major> af[4];
            wmma::fragment<wmma::matrix_b, 16, 16, 16, __nv_bfloat16, wmma::col_major> bf[2];
#pragma unroll
            for (int i = 0; i < 4; ++i)
                wmma::load_matrix_sync(af[i], &As[wr * 64 + i * 16][kf * 16], SLD);
#pragma unroll
            for (int j = 0; j < 2; ++j)
                wmma::load_matrix_sync(bf[j], &Bs[wc * 32 + j * 16][kf * 16], SLD);
#pragma unroll
            for (int i = 0; i < 4; ++i)
#pragma unroll
                for (int j = 0; j < 2; ++j)
                    wmma::mma_sync(acc[i][j], af[i], bf[j], acc[i][j]);
        }
        __syncthreads();
    }

    // epilogue: threshold G >= 0.5 * n_i * n_j, emit both orientations
    int coln = j0 + wc * 32 + lane;
    bool colok = coln < NN;
    float nj = colok ? g_norm[b * NN + coln] : 0.f;
    int word_idx = (j0 + wc * 32) >> 5;
#pragma unroll
    for (int fi = 0; fi < 4; ++fi) {
        wmma::store_matrix_sync(&stage[wid][0][0],  acc[fi][0], 40, wmma::mem_row_major);
        wmma::store_matrix_sync(&stage[wid][0][16], acc[fi][1], 40, wmma::mem_row_major);
        __syncwarp();
        int rowbase = i0 + wr * 64 + fi * 16;
        for (int rr = 0; rr < 16; ++rr) {
            int row = rowbase + rr;
            bool rowok = row < NN;
            float ni  = rowok ? g_norm[b * NN + row] : 0.f;
            float val = stage[wid][rr][lane];
            bool pred = rowok && colok && (val >= 0.5f * ni * nj);
            unsigned wbits = __ballot_sync(0xFFFFFFFFu, pred);
            if (lane == 0) {
                wbits_s[wid][fi * 16 + rr] = wbits;
                if (rowok) g_Asim[((size_t)b * NN + row) * NWRD + word_idx] = wbits;
            }
        }
        __syncwarp();
    }
    // transposed orientation: rows = this warp's cols, words = this warp's rows
    unsigned t0 = 0, t1 = 0;
#pragma unroll
    for (int r2 = 0; r2 < 32; ++r2) {
        t0 |= ((wbits_s[wid][r2]      >> lane) & 1u) << r2;
        t1 |= ((wbits_s[wid][r2 + 32] >> lane) & 1u) << r2;
    }
    if (colok) {
        int wi = (i0 + wr * 64) >> 5;
        size_t base = ((size_t)b * NN + coln) * NWRD;
        g_Asim[base + wi]     = t0;
        g_Asim[base + wi + 1] = t1;
    }
}

// ---------------- 4) Z = (x @ [W1c|W1d]) * inv_s  (bf16 split tensor GEMM) ----------------
#define ZM 128
#define ZN 96
#define ZK 32
#define ZLDA 48
#define ZLDB 112
__global__ __launch_bounds__(384) void z_kernel_tc() {
    __shared__ __align__(32) __nv_bfloat16 Ah[ZM][ZLDA];
    __shared__ __align__(32) __nv_bfloat16 Al[ZM][ZLDA];
    __shared__ __align__(32) __nv_bfloat16 Wh_s[ZK][ZLDB];
    __shared__ __align__(32) __nv_bfloat16 Wl_s[ZK][ZLDB];

    int tid = threadIdx.x;
    int wid = tid >> 5, lane = tid & 31;
    int wr = wid / 3, wc = wid % 3;                     // 4 x 3 warps, 32x32 each
    int row0 = blockIdx.x * ZM;                         // flat rows [0, 16000)

    wmma::fragment<wmma::accumulator, 16, 16, 16, float> acc[2][2];
#pragma unroll
    for (int i = 0; i < 2; ++i)
#pragma unroll
        for (int j = 0; j < 2; ++j) wmma::fill_fragment(acc[i][j], 0.f);

    for (int k0 = 0; k0 < CC; k0 += ZK) {
        // A tiles: 128 rows x 32 cols, hi+lo (512 uint4 each)
        for (int idx = tid; idx < (ZM * ZK) / 8; idx += 384) {
            int row = idx >> 2, seg = (idx & 3) * 8;
            size_t off = (size_t)(row0 + row) * CC + k0 + seg;
            *(uint4*)&Ah[row][seg] = *(const uint4*)(g_xb + off);
            *(uint4*)&Al[row][seg] = *(const uint4*)(g_xl + off);
        }
        // W tiles: 32 rows x 96 cols, hi+lo (192 uint4 each)
        for (int idx = tid; idx < (ZK * ZN) / 8; idx += 384) {
            int row = idx / 12, seg = (idx % 12) * 8;
            size_t off = (size_t)(k0 + row) * ZN + seg;
            *(uint4*)&Wh_s[row][seg] = *(const uint4*)(g_Wh + off);
            *(uint4*)&Wl_s[row][seg] = *(const uint4*)(g_Wl + off);
        }
        __syncthreads();
#pragma unroll
        for (int ks = 0; ks < 2; ++ks) {
            wmma::fragment<wmma::matrix_a, 16, 16, 16, __nv_bfloat16, wmma::row_major> ah[2], al[2];
            wmma::fragment<wmma::matrix_b, 16, 16, 16, __nv_bfloat16, wmma::row_major> bh[2], bl[2];
#pragma unroll
            for (int i = 0; i < 2; ++i) {
                wmma::load_matrix_sync(ah[i], &Ah[wr * 32 + i * 16][ks * 16], ZLDA);
                wmma::load_matrix_sync(al[i], &Al[wr * 32 + i * 16][ks * 16], ZLDA);
            }
#pragma unroll
            for (int j = 0; j < 2; ++j) {
                wmma::load_matrix_sync(bh[j], &Wh_s[ks * 16][wc * 32 + j * 16], ZLDB);
                wmma::load_matrix_sync(bl[j], &Wl_s[ks * 16][wc * 32 + j * 16], ZLDB);
            }
#pragma unroll
            for (int i = 0; i < 2; ++i)
#pragma unroll
                for (int j = 0; j < 2; ++j) {
                    wmma::mma_sync(acc[i][j], ah[i], bh[j], acc[i][j]);
                    wmma::mma_sync(acc[i][j], ah[i], bl[j], acc[i][j]);
                    wmma::mma_sync(acc[i][j], al[i], bh[j], acc[i][j]);
                }
        }
        __syncthreads();
    }

    // epilogue: stage per warp (alias onto Ah), scale by inv_s, write cols < 84
    __syncthreads();
    float* ws = (float*)&Ah[0][0] + wid * 256;          // 16x16 per warp
#pragma unroll
    for (int i = 0; i < 2; ++i)
#pragma unroll
        for (int j = 0; j < 2; ++j) {
            wmma::store_matrix_sync(ws, acc[i][j], 16, wmma::mem_row_major);
            __syncwarp();
            int grow0 = row0 + wr * 32 + i * 16;
            int gcol0 = wc * 32 + j * 16;
            for (int e = lane; e < 256; e += 32) {
                int rr = e >> 4, cc = e & 15;
                int gc = gcol0 + cc;
                if (gc < F2) {
                    int gr = grow0 + rr;
                    g_Z[(size_t)gr * F2 + gc] = ws[e] * g_inv_s[gr];
                }
            }
            __syncwarp();
        }
}

// ---------------- 5) H = relu(A @ Z + b1) ----------------
__global__ void agg1_kernel(const float* __restrict__ b1c, const float* __restrict__ b1d) {
    int i = blockIdx.x, br = blockIdx.y, b = blockIdx.z;
    __shared__ unsigned wds[NWRD];
    int t = threadIdx.x;                                 // 64
    const unsigned* A = (br ? g_Asim : g_Aadj) + ((size_t)b * NN + i) * NWRD;
    if (t < NWRD) wds[t] = A[t];
    __syncthreads();
    if (t >= HID) return;
    float acc = 0.f;
    const float* Zb = g_Z + (size_t)b * NN * F2 + br * HID;
    for (int w = 0; w < NWRD; ++w) {
        unsigned m = wds[w];
        while (m) {
            int j = w * 32 + __ffs(m) - 1;
            m &= m - 1;
            acc += Zb[(size_t)j * F2 + t];
        }
    }
    float bias = br ? b1d[t] : b1c[t];
    g_H[((size_t)b * NN + i) * F2 + br * HID + t] = fmaxf(acc + bias, 0.f);
}

// ---------------- 6) T = H @ [W_cls2 | W_det2] ----------------
__global__ void t_kernel(const float* __restrict__ W2c, const float* __restrict__ W2d) {
    int g = blockIdx.x * blockDim.x + threadIdx.x;
    if (g >= BB * NN * 40) return;
    int c40 = g % 40; int i = g / 40;
    int br = c40 / 20, c = c40 % 20;
    const float* W = br ? W2d : W2c;
    const float* h = g_H + (size_t)i * F2 + br * HID;
    float acc = 0.f;
#pragma unroll
    for (int f = 0; f < HID; ++f) acc += h[f] * W[f * NCLS + c];
    g_T[(size_t)i * 40 + c40] = acc;
}

// ---------------- 7) out_pre = A @ T + b2 ----------------
__global__ void agg2_kernel(const float* __restrict__ b2c, const float* __restrict__ b2d,
                            float* __restrict__ out) {
    int i = blockIdx.x, br = blockIdx.y, b = blockIdx.z;
    __shared__ unsigned wds[NWRD];
    int t = threadIdx.x;                                 // 32
    const unsigned* A = (br ? g_Asim : g_Aadj) + ((size_t)b * NN + i) * NWRD;
    wds[t] = A[t]; wds[t + 32] = A[t + 32];
    __syncthreads();
    if (t >= NCLS) return;
    float acc = 0.f;
    const float* Tb = g_T + (size_t)b * NN * 40 + br * NCLS;
    for (int w = 0; w < NWRD; ++w) {
        unsigned m = wds[w];
        while (m) {
            int j = w * 32 + __ffs(m) - 1;
            m &= m - 1;
            acc += Tb[(size_t)j * 40 + t];
        }
    }
    acc += br ? b2d[t] : b2c[t];
    out[(size_t)br * BB * NN * NCLS + ((size_t)b * NN + i) * NCLS + t] = acc;
}

// ---------------- 8) softmax over classes (cls half) ----------------
__global__ void softmax_cls(float* __restrict__ out) {
    int rrow = blockIdx.x * blockDim.x + threadIdx.x;
    if (rrow >= BB * NN) return;
    float* p = out + (size_t)rrow * NCLS;
    float mx = -1e30f;
#pragma unroll
    for (int c = 0; c < NCLS; ++c) mx = fmaxf(mx, p[c]);
    float e[NCLS]; float s = 0.f;
#pragma unroll
    for (int c = 0; c < NCLS; ++c) { e[c] = expf(p[c] - mx); s += e[c]; }
    float inv = 1.f / s;
#pragma unroll
    for (int c = 0; c < NCLS; ++c) p[c] = e[c] * inv;
}

// ---------------- 9) softmax over proposals (det half, per (b, class)) ----------------
__global__ void softmax_det(float* __restrict__ out) {
    int b = blockIdx.x / NCLS, c = blockIdx.x % NCLS;
    float* p = out + (size_t)BB * NN * NCLS + (size_t)b * NN * NCLS + c;
    __shared__ float buf[NN];
    __shared__ float red[256];
    int t = threadIdx.x;
    float mx = -1e30f;
    for (int j = t; j < NN; j += 256) {
        float v = p[(size_t)j * NCLS];
        buf[j] = v;
        mx = fmaxf(mx, v);
    }
    red[t] = mx; __syncthreads();
    for (int off = 128; off > 0; off >>= 1) {
        if (t < off) red[t] = fmaxf(red[t], red[t + off]);
        __syncthreads();
    }
    mx = red[0];
    __syncthreads();
    float s = 0.f;
    for (int j = t; j < NN; j += 256) {
        float e = expf(buf[j] - mx);
        buf[j] = e;
        s += e;
    }
    red[t] = s; __syncthreads();
    for (int off = 128; off > 0; off >>= 1) {
        if (t < off) red[t] += red[t + off];
        __syncthreads();
    }
    float inv = 1.f / red[0];
    for (int j = t; j < NN; j += 256) p[(size_t)j * NCLS] = buf[j] * inv;
}

// ---------------- launcher ----------------
extern "C" void kernel_launch(void* const* d_in, const int* in_sizes, int n_in,
                              void* d_out, int out_size) {
    const float* x1    = (const float*)d_in[0];
    const float* boxes = (const float*)d_in[2];
    const float* Wc1   = (const float*)d_in[3];
    const float* bc1   = (const float*)d_in[4];
    const float* Wc2   = (const float*)d_in[5];
    const float* bc2   = (const float*)d_in[6];
    const float* Wd1   = (const float*)d_in[7];
    const float* bd1   = (const float*)d_in[8];
    const float* Wd2   = (const float*)d_in[9];
    const float* bd2   = (const float*)d_in[10];
    float* out = (float*)d_out;

    prep_kernel<<<BB * NN, 128>>>(x1);
    wprep_kernel<<<(4096 * 96 + 255) / 256, 256>>>(Wc1, Wd1);
    iou_kernel<<<dim3(NN / 4, BB), 256>>>(boxes);
    sim_kernel<<<dim3(NTIL * (NTIL + 1) / 2, 1, BB), 256>>>();
    z_kernel_tc<<<(BB * NN + ZM - 1) / ZM, 384>>>();
    agg1_kernel<<<dim3(NN, 2, BB), 64>>>(bc1, bd1);
    t_kernel<<<(BB * NN * 40 + 255) / 256, 256>>>(Wc2, Wd2);
    agg2_kernel<<<dim3(NN, 2, BB), 32>>>(bc2, bd2, out);
    softmax_cls<<<(BB * NN + 255) / 256, 256>>>(out);
    softmax_det<<<BB * NCLS, 256>>>(out);
}

// round 12
// speedup vs baseline: 1.9664x; 1.0925x over previous
#include <cuda_runtime.h>
#include <cuda_bf16.h>
#include <mma.h>
#include <cstdint>

using namespace nvcuda;

#define BB   8
#define NN   2000
#define CC   4096
#define HID  42
#define NCLS 20
#define NWRD 64          // 64 * 32 = 2048 bits >= 2000
#define F2   84          // 2*HID
#define THRESHF 0.5f
#define EPSF 1e-12f

// ---------------- scratch (device globals: allocation-free) ----------------
__device__ __nv_bfloat16 g_xb[(size_t)BB * NN * CC];     // bf16 hi of x1
__device__ __nv_bfloat16 g_xl[(size_t)BB * NN * CC];     // bf16 lo residual of x1
__device__ float    g_inv_s[BB * NN];                    // 1/rowsum (0 if sum==0)
__device__ float    g_norm[BB * NN];                     // max(||x_i||, EPS)
__device__ unsigned g_Aadj[(size_t)BB * NN * NWRD];      // IoU adjacency bitmask
__device__ unsigned g_Asim[(size_t)BB * NN * NWRD];      // cosine-sim adjacency bitmask
__device__ float    g_Z[(size_t)BB * NN * F2];           // (x @ [W_cls1|W_det1]) * inv_s
__device__ float    g_H[(size_t)BB * NN * F2];           // relu(A @ Z + b1)
__device__ float    g_T[(size_t)BB * NN * 40];           // H @ [W_cls2 | W_det2]
__device__ __nv_bfloat16 g_Wh[4096 * 96];                // [W_cls1|W_det1|0pad] hi
__device__ __nv_bfloat16 g_Wl[4096 * 96];                // lo

// ---------------- 1) row stats + bf16 hi/lo convert ----------------
__global__ void prep_kernel(const float* __restrict__ x) {
    int row = blockIdx.x;
    const float4* p = (const float4*)(x + (size_t)row * CC);
    __nv_bfloat162* q  = (__nv_bfloat162*)(g_xb + (size_t)row * CC);
    __nv_bfloat162* ql = (__nv_bfloat162*)(g_xl + (size_t)row * CC);
    int t = threadIdx.x;                                // 128
    float s = 0.f, sq = 0.f;
#pragma unroll
    for (int it = 0; it < (CC / 4) / 128; ++it) {
        int i4 = t + it * 128;
        float4 v = p[i4];
        s  += v.x + v.y + v.z + v.w;
        sq += v.x * v.x + v.y * v.y + v.z * v.z + v.w * v.w;
        __nv_bfloat162 h0 = __floats2bfloat162_rn(v.x, v.y);
        __nv_bfloat162 h1 = __floats2bfloat162_rn(v.z, v.w);
        q[i4 * 2]     = h0;
        q[i4 * 2 + 1] = h1;
        __nv_bfloat162 l0 = __floats2bfloat162_rn(v.x - __bfloat162float(h0.x),
                                                  v.y - __bfloat162float(h0.y));
        __nv_bfloat162 l1 = __floats2bfloat162_rn(v.z - __bfloat162float(h1.x),
                                                  v.w - __bfloat162float(h1.y));
        ql[i4 * 2]     = l0;
        ql[i4 * 2 + 1] = l1;
    }
    __shared__ float ss[128], sqq[128];
    ss[t] = s; sqq[t] = sq;
    __syncthreads();
    for (int off = 64; off > 0; off >>= 1) {
        if (t < off) { ss[t] += ss[t + off]; sqq[t] += sqq[t + off]; }
        __syncthreads();
    }
    if (t == 0) {
        float sum = ss[0];
        g_inv_s[row] = (sum == 0.f) ? 0.f : (1.f / sum);
        g_norm[row]  = fmaxf(sqrtf(sqq[0]), EPSF);
    }
}

// ---------------- 1b) weight hi/lo prep ----------------
__global__ void wprep_kernel(const float* __restrict__ Wc, const float* __restrict__ Wd) {
    int idx = blockIdx.x * blockDim.x + threadIdx.x;
    if (idx >= 4096 * 96) return;
    int k = idx / 96, c = idx % 96;
    float v = 0.f;
    if (c < HID)      v = Wc[k * HID + c];
    else if (c < F2)  v = Wd[k * HID + c - HID];
    __nv_bfloat16 h = __float2bfloat16(v);
    g_Wh[idx] = h;
    g_Wl[idx] = __float2bfloat16(v - __bfloat162float(h));
}

// ---------------- 2) pairwise IoU -> A_adj bitmask ----------------
__global__ void iou_kernel(const float* __restrict__ boxes) {
    int b = blockIdx.y;
    __shared__ float4 bx[NN];
    int t = threadIdx.x;                                // 256
    const float4* src = (const float4*)boxes + (size_t)b * NN;
    for (int idx = t; idx < NN; idx += 256) bx[idx] = src[idx];
    __syncthreads();

    int i = blockIdx.x * 4 + (t >> 6);
    int w = t & 63;
    float4 bi = bx[i];
    float ai = __fmul_rn(__fsub_rn(bi.z, bi.x), __fsub_rn(bi.w, bi.y));
    unsigned word = 0;
#pragma unroll 4
    for (int k = 0; k < 32; ++k) {
        int j = w * 32 + k;
        if (j < NN) {
            float4 bj = bx[j];
            float aj  = __fmul_rn(__fsub_rn(bj.z, bj.x), __fsub_rn(bj.w, bj.y));
            float ltx = fmaxf(bi.x, bj.x), lty = fmaxf(bi.y, bj.y);
            float rbx = fminf(bi.z, bj.z), rby = fminf(bi.w, bj.w);
            float wx  = fmaxf(__fsub_rn(rbx, ltx), 0.f);
            float wy  = fmaxf(__fsub_rn(rby, lty), 0.f);
            float inter = __fmul_rn(wx, wy);
            float uni   = __fsub_rn(__fadd_rn(ai, aj), inter);
            float iou   = inter / fmaxf(uni, EPSF);
            if (iou >= THRESHF) word |= (1u << k);
        }
    }
    g_Aadj[((size_t)b * NN + i) * NWRD + w] = word;
}

// ---------------- 3) sim: G = x x^T, WMMA 256x128 block / 64x64 warp tile ----------------
// grid.x = 72 (36 upper-tri 256x256 supertiles * 2 col-halves), grid.z = images
#define SBK 32
#define SLD 40           // 80B pitch: conflict-free ldmatrix row starts
#define APITCH (256 * SLD)
#define BPITCH (128 * SLD)
#define STGLD 36

__global__ __launch_bounds__(256, 1) void sim_kernel() {
    extern __shared__ __nv_bfloat16 sm[];               // As[2]: 2*APITCH, Bs[2]: 2*BPITCH
    __nv_bfloat16* As = sm;
    __nv_bfloat16* Bs = sm + 2 * APITCH;
    __shared__ float rownorm[256];
    __shared__ float colnorm[128];

    int tid = threadIdx.x, wid = tid >> 5, lane = tid & 31;
    int wr = wid >> 1, wc = wid & 1;                    // 4x2 warps of 64x64
    int b = blockIdx.z;
    int st = blockIdx.x >> 1, h = blockIdx.x & 1;
    int si = 0, rem = st;
    while (rem >= 8 - si) { rem -= (8 - si); ++si; }
    int sj = si + rem;
    int i0  = si * 256;
    int j0c = sj * 256 + h * 128;

    if (tid < 256) rownorm[tid] = (i0 + tid < NN) ? g_norm[b * NN + i0 + tid] : 0.f;
    if (tid < 128) colnorm[tid] = (j0c + tid < NN) ? g_norm[b * NN + j0c + tid] : 0.f;

    wmma::fragment<wmma::accumulator, 16, 16, 16, float> acc[4][4];
#pragma unroll
    for (int i = 0; i < 4; ++i)
#pragma unroll
        for (int j = 0; j < 4; ++j) wmma::fill_fragment(acc[i][j], 0.f);

    const __nv_bfloat16* xb = g_xb + (size_t)b * NN * CC;

    // register-staged double-buffer pipeline
    uint4 ra[4], rb[2];
    {
#pragma unroll
        for (int i = 0; i < 4; ++i) {
            int idx = tid + i * 256, row = idx >> 2, ch = idx & 3;
            ra[i] = (i0 + row < NN) ? *(const uint4*)(xb + (size_t)(i0 + row) * CC + ch * 8)
                                    : make_uint4(0, 0, 0, 0);
        }
#pragma unroll
        for (int i = 0; i < 2; ++i) {
            int idx = tid + i * 256, row = idx >> 2, ch = idx & 3;
            rb[i] = (j0c + row < NN) ? *(const uint4*)(xb + (size_t)(j0c + row) * CC + ch * 8)
                                     : make_uint4(0, 0, 0, 0);
        }
#pragma unroll
        for (int i = 0; i < 4; ++i) {
            int idx = tid + i * 256, row = idx >> 2, ch = idx & 3;
            *(uint4*)&As[row * SLD + ch * 8] = ra[i];
        }
#pragma unroll
        for (int i = 0; i < 2; ++i) {
            int idx = tid + i * 256, row = idx >> 2, ch = idx & 3;
            *(uint4*)&Bs[row * SLD + ch * 8] = rb[i];
        }
    }
    __syncthreads();

    for (int kb = 0; kb < CC / SBK; ++kb) {
        int cur = kb & 1, nxt = cur ^ 1;
        bool more = kb + 1 < CC / SBK;
        if (more) {
            int k0 = (kb + 1) * SBK;
#pragma unroll
            for (int i = 0; i < 4; ++i) {
                int idx = tid + i * 256, row = idx >> 2, ch = idx & 3;
                ra[i] = (i0 + row < NN) ? *(const uint4*)(xb + (size_t)(i0 + row) * CC + k0 + ch * 8)
                                        : make_uint4(0, 0, 0, 0);
            }
#pragma unroll
            for (int i = 0; i < 2; ++i) {
                int idx = tid + i * 256, row = idx >> 2, ch = idx & 3;
                rb[i] = (j0c + row < NN) ? *(const uint4*)(xb + (size_t)(j0c + row) * CC + k0 + ch * 8)
                                         : make_uint4(0, 0, 0, 0);
            }
        }
        const __nv_bfloat16* Ac = As + cur * APITCH;
        const __nv_bfloat16* Bc = Bs + cur * BPITCH;
#pragma unroll
        for (int kf = 0; kf < 2; ++kf) {
            wmma::fragment<wmma::matrix_a, 16, 16, 16, __nv_bfloat16, wmma::row_major> af[4];
            wmma::fragment<wmma::matrix_b, 16, 16, 16, __nv_bfloat16, wmma::col_major> bf[4];
#pragma unroll
            for (int i = 0; i < 4; ++i)
                wmma::load_matrix_sync(af[i], Ac + (wr * 64 + i * 16) * SLD + kf * 16, SLD);
#pragma unroll
            for (int j = 0; j < 4; ++j)
                wmma::load_matrix_sync(bf[j], Bc + (wc * 64 + j * 16) * SLD + kf * 16, SLD);
#pragma unroll
            for (int i = 0; i < 4; ++i)
#pragma unroll
                for (int j = 0; j < 4; ++j)
                    wmma::mma_sync(acc[i][j], af[i], bf[j], acc[i][j]);
        }
        if (more) {
#pragma unroll
            for (int i = 0; i < 4; ++i) {
                int idx = tid + i * 256, row = idx >> 2, ch = idx & 3;
                *(uint4*)&As[nxt * APITCH + row * SLD + ch * 8] = ra[i];
            }
#pragma unroll
            for (int i = 0; i < 2; ++i) {
                int idx = tid + i * 256, row = idx >> 2, ch = idx & 3;
                *(uint4*)&Bs[nxt * BPITCH + row * SLD + ch * 8] = rb[i];
            }
        }
        __syncthreads();
    }

    // epilogue: threshold + bit words, both orientations. Reuse smem as stage.
    float* stage = (float*)sm + wid * (16 * STGLD);     // 16x36 floats per warp
#pragma unroll
    for (int jw = 0; jw < 2; ++jw) {
        int col = j0c + wc * 64 + jw * 32 + lane;
        bool colok = col < NN;
        float nj = colnorm[wc * 64 + jw * 32 + lane];
        unsigned mw0 = 0, mw1 = 0;
#pragma unroll
        for (int i = 0; i < 4; ++i) {
            wmma::store_matrix_sync(stage,      acc[i][jw * 2],     STGLD, wmma::mem_row_major);
            wmma::store_matrix_sync(stage + 16, acc[i][jw * 2 + 1], STGLD, wmma::mem_row_major);
            __syncwarp();
            for (int rr = 0; rr < 16; ++rr) {
                int lr = wr * 64 + i * 16 + rr;         // local row 0..255
                int row = i0 + lr;
                bool rowok = row < NN;
                float ni = rownorm[lr];
                float val = stage[rr * STGLD + lane];
                bool pred = rowok && colok && (val >= 0.5f * ni * nj);
                unsigned word = __ballot_sync(0xFFFFFFFFu, pred);
                if (lane == 0 && rowok)
                    g_Asim[((size_t)b * NN + row) * NWRD + ((j0c + wc * 64 + jw * 32) >> 5)] = word;
                int lrr = i * 16 + rr;                  // 0..63 within warp rows
                if (lrr < 32) mw0 |= (pred ? 1u : 0u) << lrr;
                else          mw1 |= (pred ? 1u : 0u) << (lrr - 32);
            }
            __syncwarp();
        }
        if (colok) {
            size_t base = ((size_t)b * NN + col) * NWRD + ((i0 + wr * 64) >> 5);
            g_Asim[base]     = mw0;
            g_Asim[base + 1] = mw1;
        }
    }
}

// ---------------- 4) Z = (x @ [W1c|W1d]) * inv_s (bf16 split, double-buffered) ----------------
#define ZM 128
#define ZN 96
#define ZK 32
#define ZLDA 40                      // 32 + 8 pad (halves)
#define ZLDB 104                     // 96 + 8 pad
#define ZAP (ZM * ZLDA)              // A stage pitch (elems) = 5120
#define ZWP (ZK * ZLDB)              // W stage pitch (elems) = 3328

__global__ void __launch_bounds__(384, 1) z_kernel_tc() {
    extern __shared__ __nv_bfloat16 zsm[];
    __nv_bfloat16* Ah = zsm;                     // 2 * ZAP
    __nv_bfloat16* Al = zsm + 2 * ZAP;           // 2 * ZAP
    __nv_bfloat16* Wh = zsm + 4 * ZAP;           // 2 * ZWP
    __nv_bfloat16* Wl = zsm + 4 * ZAP + 2 * ZWP; // 2 * ZWP

    int tid = threadIdx.x;
    int wid = tid >> 5, lane = tid & 31;
    int wr = wid / 3, wc = wid % 3;              // 4 x 3 warps, 32x32 tiles
    int row0 = blockIdx.x * ZM;                  // 125 blocks cover 16000 rows exactly

    wmma::fragment<wmma::accumulator, 16, 16, 16, float> acc[2][2];
#pragma unroll
    for (int i = 0; i < 2; ++i)
#pragma unroll
        for (int j = 0; j < 2; ++j) wmma::fill_fragment(acc[i][j], 0.f);

    // staging registers: A 512 uint4 (hi+lo), W 384 uint4 (hi+lo)
    uint4 rah[2], ral[2], rwh, rwl;
    {
#pragma unroll
        for (int i = 0; i < 2; ++i) {
            int idx = tid + i * 384;
            if (idx < 512) {
                int row = idx >> 2, ch = idx & 3;
                size_t off = (size_t)(row0 + row) * CC + ch * 8;
                rah[i] = *(const uint4*)(g_xb + off);
                ral[i] = *(const uint4*)(g_xl + off);
            }
        }
        {
            int row = tid / 12, cs = tid % 12;
            size_t off = (size_t)row * ZN + cs * 8;
            rwh = *(const uint4*)(g_Wh + off);
            rwl = *(const uint4*)(g_Wl + off);
        }
#pragma unroll
        for (int i = 0; i < 2; ++i) {
            int idx = tid + i * 384;
            if (idx < 512) {
                int row = idx >> 2, ch = idx & 3;
                *(uint4*)&Ah[row * ZLDA + ch * 8] = rah[i];
                *(uint4*)&Al[row * ZLDA + ch * 8] = ral[i];
            }
        }
        {
            int row = tid / 12, cs = tid % 12;
            *(uint4*)&Wh[row * ZLDB + cs * 8] = rwh;
            *(uint4*)&Wl[row * ZLDB + cs * 8] = rwl;
        }
    }
    __syncthreads();

    for (int kb = 0; kb < CC / ZK; ++kb) {
        int cur = kb & 1, nxt = cur ^ 1;
        bool more = kb + 1 < CC / ZK;
        if (more) {
            int k0 = (kb + 1) * ZK;
#pragma unroll
            for (int i = 0; i < 2; ++i) {
                int idx = tid + i * 384;
                if (idx < 512) {
                    int row = idx >> 2, ch = idx & 3;
                    size_t off = (size_t)(row0 + row) * CC + k0 + ch * 8;
                    rah[i] = *(const uint4*)(g_xb + off);
                    ral[i] = *(const uint4*)(g_xl + off);
                }
            }
            {
                int row = tid / 12, cs = tid % 12;
                size_t off = (size_t)(k0 + row) * ZN + cs * 8;
                rwh = *(const uint4*)(g_Wh + off);
                rwl = *(const uint4*)(g_Wl + off);
            }
        }
        const __nv_bfloat16* Ahc = Ah + cur * ZAP;
        const __nv_bfloat16* Alc = Al + cur * ZAP;
        const __nv_bfloat16* Whc = Wh + cur * ZWP;
        const __nv_bfloat16* Wlc = Wl + cur * ZWP;
#pragma unroll
        for (int ks = 0; ks < 2; ++ks) {
            wmma::fragment<wmma::matrix_a, 16, 16, 16, __nv_bfloat16, wmma::row_major> ah[2], al[2];
            wmma::fragment<wmma::matrix_b, 16, 16, 16, __nv_bfloat16, wmma::row_major> bh[2], bl[2];
#pragma unroll
            for (int i = 0; i < 2; ++i) {
                wmma::load_matrix_sync(ah[i], Ahc + (wr * 32 + i * 16) * ZLDA + ks * 16, ZLDA);
                wmma::load_matrix_sync(al[i], Alc + (wr * 32 + i * 16) * ZLDA + ks * 16, ZLDA);
            }
#pragma unroll
            for (int j = 0; j < 2; ++j) {
                wmma::load_matrix_sync(bh[j], Whc + (ks * 16) * ZLDB + wc * 32 + j * 16, ZLDB);
                wmma::load_matrix_sync(bl[j], Wlc + (ks * 16) * ZLDB + wc * 32 + j * 16, ZLDB);
            }
#pragma unroll
            for (int i = 0; i < 2; ++i)
#pragma unroll
                for (int j = 0; j < 2; ++j) {
                    wmma::mma_sync(acc[i][j], ah[i], bh[j], acc[i][j]);
                    wmma::mma_sync(acc[i][j], ah[i], bl[j], acc[i][j]);
                    wmma::mma_sync(acc[i][j], al[i], bh[j], acc[i][j]);
                }
        }
        if (more) {
#pragma unroll
            for (int i = 0; i < 2; ++i) {
                int idx = tid + i * 384;
                if (idx < 512) {
                    int row = idx >> 2, ch = idx & 3;
                    *(uint4*)&Ah[nxt * ZAP + row * ZLDA + ch * 8] = rah[i];
                    *(uint4*)&Al[nxt * ZAP + row * ZLDA + ch * 8] = ral[i];
                }
            }
            {
                int row = tid / 12, cs = tid % 12;
                *(uint4*)&Wh[nxt * ZWP + row * ZLDB + cs * 8] = rwh;
                *(uint4*)&Wl[nxt * ZWP + row * ZLDB + cs * 8] = rwl;
            }
        }
        __syncthreads();
    }

    // epilogue: stage per warp (alias onto zsm), scale by inv_s, write cols < 84
    float* ws = (float*)zsm + wid * 256;
#pragma unroll
    for (int i = 0; i < 2; ++i)
#pragma unroll
        for (int j = 0; j < 2; ++j) {
            wmma::store_matrix_sync(ws, acc[i][j], 16, wmma::mem_row_major);
            __syncwarp();
            int grow0 = row0 + wr * 32 + i * 16;
            int gcol0 = wc * 32 + j * 16;
            for (int e = lane; e < 256; e += 32) {
                int rr = e >> 4, cc = e & 15;
                int gc = gcol0 + cc;
                if (gc < F2) {
                    int gr = grow0 + rr;
                    g_Z[(size_t)gr * F2 + gc] = ws[e] * g_inv_s[gr];
                }
            }
            __syncwarp();
        }
}

// ---------------- 5) H = relu(A @ Z + b1) ----------------
__global__ void agg1_kernel(const float* __restrict__ b1c, const float* __restrict__ b1d) {
    int i = blockIdx.x, br = blockIdx.y, b = blockIdx.z;
    __shared__ unsigned wds[NWRD];
    int t = threadIdx.x;                                 // 64
    const unsigned* A = (br ? g_Asim : g_Aadj) + ((size_t)b * NN + i) * NWRD;
    if (t < NWRD) wds[t] = A[t];
    __syncthreads();
    if (t >= HID) return;
    float acc = 0.f;
    const float* Zb = g_Z + (size_t)b * NN * F2 + br * HID;
    for (int w = 0; w < NWRD; ++w) {
        unsigned m = wds[w];
        while (m) {
            int j = w * 32 + __ffs(m) - 1;
            m &= m - 1;
            acc += Zb[(size_t)j * F2 + t];
        }
    }
    float bias = br ? b1d[t] : b1c[t];
    g_H[((size_t)b * NN + i) * F2 + br * HID + t] = fmaxf(acc + bias, 0.f);
}

// ---------------- 6) T = H @ [W_cls2 | W_det2] ----------------
__global__ void t_kernel(const float* __restrict__ W2c, const float* __restrict__ W2d) {
    int g = blockIdx.x * blockDim.x + threadIdx.x;
    if (g >= BB * NN * 40) return;
    int c40 = g % 40; int i = g / 40;
    int br = c40 / 20, c = c40 % 20;
    const float* W = br ? W2d : W2c;
    const float* h = g_H + (size_t)i * F2 + br * HID;
    float acc = 0.f;
#pragma unroll
    for (int f = 0; f < HID; ++f) acc += h[f] * W[f * NCLS + c];
    g_T[(size_t)i * 40 + c40] = acc;
}

// ---------------- 7) out = A @ T + b2, cls branch: fused class softmax ----------------
__global__ void agg2_kernel(const float* __restrict__ b2c, const float* __restrict__ b2d,
                            float* __restrict__ out) {
    int i = blockIdx.x, br = blockIdx.y, b = blockIdx.z;
    __shared__ unsigned wds[NWRD];
    int t = threadIdx.x;                                 // 32
    const unsigned* A = (br ? g_Asim : g_Aadj) + ((size_t)b * NN + i) * NWRD;
    wds[t] = A[t]; wds[t + 32] = A[t + 32];
    __syncthreads();
    bool act = t < NCLS;
    float acc = 0.f;
    if (act) {
        const float* Tb = g_T + (size_t)b * NN * 40 + br * NCLS;
        for (int w = 0; w < NWRD; ++w) {
            unsigned m = wds[w];
            while (m) {
                int j = w * 32 + __ffs(m) - 1;
                m &= m - 1;
                acc += Tb[(size_t)j * 40 + t];
            }
        }
        acc += br ? b2d[t] : b2c[t];
    }
    if (br == 0) {
        float v = act ? acc : -1e30f;
        float mx = v;
#pragma unroll
        for (int off = 16; off > 0; off >>= 1)
            mx = fmaxf(mx, __shfl_xor_sync(0xFFFFFFFFu, mx, off));
        float e = act ? expf(v - mx) : 0.f;
        float s = e;
#pragma unroll
        for (int off = 16; off > 0; off >>= 1)
            s += __shfl_xor_sync(0xFFFFFFFFu, s, off);
        acc = e / s;
    }
    if (act)
        out[(size_t)br * BB * NN * NCLS + ((size_t)b * NN + i) * NCLS + t] = acc;
}

// ---------------- 8) softmax over proposals (det half, per (b, class)) ----------------
__global__ void softmax_det(float* __restrict__ out) {
    int b = blockIdx.x / NCLS, c = blockIdx.x % NCLS;
    float* p = out + (size_t)BB * NN * NCLS + (size_t)b * NN * NCLS + c;
    __shared__ float buf[NN];
    __shared__ float red[256];
    int t = threadIdx.x;
    float mx = -1e30f;
    for (int j = t; j < NN; j += 256) {
        float v = p[(size_t)j * NCLS];
        buf[j] = v;
        mx = fmaxf(mx, v);
    }
    red[t] = mx; __syncthreads();
    for (int off = 128; off > 0; off >>= 1) {
        if (t < off) red[t] = fmaxf(red[t], red[t + off]);
        __syncthreads();
    }
    mx = red[0];
    __syncthreads();
    float s = 0.f;
    for (int j = t; j < NN; j += 256) {
        float e = expf(buf[j] - mx);
        buf[j] = e;
        s += e;
    }
    red[t] = s; __syncthreads();
    for (int off = 128; off > 0; off >>= 1) {
        if (t < off) red[t] += red[t + off];
        __syncthreads();
    }
    float inv = 1.f / red[0];
    for (int j = t; j < NN; j += 256) p[(size_t)j * NCLS] = buf[j] * inv;
}

// ---------------- launcher ----------------
extern "C" void kernel_launch(void* const* d_in, const int* in_sizes, int n_in,
                              void* d_out, int out_size) {
    const float* x1    = (const float*)d_in[0];
    const float* boxes = (const float*)d_in[2];
    const float* Wc1   = (const float*)d_in[3];
    const float* bc1   = (const float*)d_in[4];
    const float* Wc2   = (const float*)d_in[5];
    const float* bc2   = (const float*)d_in[6];
    const float* Wd1   = (const float*)d_in[7];
    const float* bd1   = (const float*)d_in[8];
    const float* Wd2   = (const float*)d_in[9];
    const float* bd2   = (const float*)d_in[10];
    float* out = (float*)d_out;

    const int simSmem = (2 * APITCH + 2 * BPITCH) * (int)sizeof(__nv_bfloat16);  // 61440
    cudaFuncSetAttribute(sim_kernel, cudaFuncAttributeMaxDynamicSharedMemorySize, simSmem);
    const int zSmem = (4 * ZAP + 4 * ZWP) * (int)sizeof(__nv_bfloat16);          // 67584
    cudaFuncSetAttribute(z_kernel_tc, cudaFuncAttributeMaxDynamicSharedMemorySize, zSmem);

    prep_kernel<<<BB * NN, 128>>>(x1);
    wprep_kernel<<<(4096 * 96 + 255) / 256, 256>>>(Wc1, Wd1);
    iou_kernel<<<dim3(NN / 4, BB), 256>>>(boxes);
    sim_kernel<<<dim3(72, 1, BB), 256, simSmem>>>();
    z_kernel_tc<<<(BB * NN) / ZM, 384, zSmem>>>();
    agg1_kernel<<<dim3(NN, 2, BB), 64>>>(bc1, bd1);
    t_kernel<<<(BB * NN * 40 + 255) / 256, 256>>>(Wc2, Wd2);
    agg2_kernel<<<dim3(NN, 2, BB), 32>>>(bc2, bd2, out);
    softmax_det<<<BB * NCLS, 256>>>(out);
}

// round 13
// speedup vs baseline: 2.1293x; 1.0828x over previous
#include <cuda_runtime.h>
#include <cuda_bf16.h>
#include <mma.h>
#include <cstdint>

using namespace nvcuda;

#define BB   8
#define NN   2000
#define CC   4096
#define HID  42
#define NCLS 20
#define NWRD 64          // 64 * 32 = 2048 bits >= 2000
#define F2   84          // 2*HID
#define THRESHF 0.5f
#define EPSF 1e-12f

// ---------------- scratch (device globals: allocation-free) ----------------
__device__ __nv_bfloat16 g_xb[(size_t)BB * NN * CC];     // bf16 hi of x1
__device__ __nv_bfloat16 g_xl[(size_t)BB * NN * CC];     // bf16 lo residual of x1
__device__ float    g_inv_s[BB * NN];                    // 1/rowsum (0 if sum==0)
__device__ float    g_norm[BB * NN];                     // max(||x_i||, EPS)
__device__ unsigned g_Aadj[(size_t)BB * NN * NWRD];      // IoU adjacency bitmask
__device__ unsigned g_Asim[(size_t)BB * NN * NWRD];      // cosine-sim adjacency bitmask
__device__ float    g_Z[(size_t)BB * NN * F2];           // (x @ [W_cls1|W_det1]) * inv_s
__device__ float    g_H[(size_t)BB * NN * F2];           // relu(A @ Z + b1)
__device__ float    g_T[(size_t)BB * NN * 40];           // H @ [W_cls2 | W_det2]
__device__ __nv_bfloat16 g_Wh[4096 * 96];                // [W_cls1|W_det1|0pad] hi
__device__ __nv_bfloat16 g_Wl[4096 * 96];                // lo

// ---------------- cp.async helpers ----------------
__device__ __forceinline__ void cp_async16(uint32_t dst, const void* src, int srcsize) {
    asm volatile("cp.async.cg.shared.global [%0], [%1], 16, %2;"
                 :: "r"(dst), "l"(src), "r"(srcsize) : "memory");
}
#define CP_COMMIT() asm volatile("cp.async.commit_group;" ::: "memory")
#define CP_WAIT1()  asm volatile("cp.async.wait_group 1;" ::: "memory")

// ---------------- 1) row stats + bf16 hi/lo convert ----------------
__global__ void prep_kernel(const float* __restrict__ x) {
    int row = blockIdx.x;
    const float4* p = (const float4*)(x + (size_t)row * CC);
    __nv_bfloat162* q  = (__nv_bfloat162*)(g_xb + (size_t)row * CC);
    __nv_bfloat162* ql = (__nv_bfloat162*)(g_xl + (size_t)row * CC);
    int t = threadIdx.x;                                // 128
    float s = 0.f, sq = 0.f;
#pragma unroll
    for (int it = 0; it < (CC / 4) / 128; ++it) {
        int i4 = t + it * 128;
        float4 v = p[i4];
        s  += v.x + v.y + v.z + v.w;
        sq += v.x * v.x + v.y * v.y + v.z * v.z + v.w * v.w;
        __nv_bfloat162 h0 = __floats2bfloat162_rn(v.x, v.y);
        __nv_bfloat162 h1 = __floats2bfloat162_rn(v.z, v.w);
        q[i4 * 2]     = h0;
        q[i4 * 2 + 1] = h1;
        __nv_bfloat162 l0 = __floats2bfloat162_rn(v.x - __bfloat162float(h0.x),
                                                  v.y - __bfloat162float(h0.y));
        __nv_bfloat162 l1 = __floats2bfloat162_rn(v.z - __bfloat162float(h1.x),
                                                  v.w - __bfloat162float(h1.y));
        ql[i4 * 2]     = l0;
        ql[i4 * 2 + 1] = l1;
    }
    __shared__ float ss[128], sqq[128];
    ss[t] = s; sqq[t] = sq;
    __syncthreads();
    for (int off = 64; off > 0; off >>= 1) {
        if (t < off) { ss[t] += ss[t + off]; sqq[t] += sqq[t + off]; }
        __syncthreads();
    }
    if (t == 0) {
        float sum = ss[0];
        g_inv_s[row] = (sum == 0.f) ? 0.f : (1.f / sum);
        g_norm[row]  = fmaxf(sqrtf(sqq[0]), EPSF);
    }
}

// ---------------- 1b) weight hi/lo prep ----------------
__global__ void wprep_kernel(const float* __restrict__ Wc, const float* __restrict__ Wd) {
    int idx = blockIdx.x * blockDim.x + threadIdx.x;
    if (idx >= 4096 * 96) return;
    int k = idx / 96, c = idx % 96;
    float v = 0.f;
    if (c < HID)      v = Wc[k * HID + c];
    else if (c < F2)  v = Wd[k * HID + c - HID];
    __nv_bfloat16 h = __float2bfloat16(v);
    g_Wh[idx] = h;
    g_Wl[idx] = __float2bfloat16(v - __bfloat162float(h));
}

// ---------------- 2) pairwise IoU -> A_adj bitmask ----------------
__global__ void iou_kernel(const float* __restrict__ boxes) {
    int b = blockIdx.y;
    __shared__ float4 bx[NN];
    int t = threadIdx.x;                                // 256
    const float4* src = (const float4*)boxes + (size_t)b * NN;
    for (int idx = t; idx < NN; idx += 256) bx[idx] = src[idx];
    __syncthreads();

    int i = blockIdx.x * 4 + (t >> 6);
    int w = t & 63;
    float4 bi = bx[i];
    float ai = __fmul_rn(__fsub_rn(bi.z, bi.x), __fsub_rn(bi.w, bi.y));
    unsigned word = 0;
#pragma unroll 4
    for (int k = 0; k < 32; ++k) {
        int j = w * 32 + k;
        if (j < NN) {
            float4 bj = bx[j];
            float aj  = __fmul_rn(__fsub_rn(bj.z, bj.x), __fsub_rn(bj.w, bj.y));
            float ltx = fmaxf(bi.x, bj.x), lty = fmaxf(bi.y, bj.y);
            float rbx = fminf(bi.z, bj.z), rby = fminf(bi.w, bj.w);
            float wx  = fmaxf(__fsub_rn(rbx, ltx), 0.f);
            float wy  = fmaxf(__fsub_rn(rby, lty), 0.f);
            float inter = __fmul_rn(wx, wy);
            float uni   = __fsub_rn(__fadd_rn(ai, aj), inter);
            float iou   = inter / fmaxf(uni, EPSF);
            if (iou >= THRESHF) word |= (1u << k);
        }
    }
    g_Aadj[((size_t)b * NN + i) * NWRD + w] = word;
}

// ---------------- 3) sim: G = x x^T, 512 thr, 256x128 block / 64x32 warp tile ----------------
// grid.x = 72 (36 upper-tri 256x256 supertiles * 2 col-halves), grid.z = images
#define SBK 32
#define SLD 40                       // 80B pitch: conflict-free ldmatrix row starts
#define APITCH (256 * SLD)           // A stage pitch, elems
#define BPITCH (128 * SLD)           // B stage pitch, elems
#define ABYTES (256 * SLD * 2)       // 20480
#define BBYTES (128 * SLD * 2)       // 10240
#define STGLD 36
#define NKB (CC / SBK)               // 128

__global__ __launch_bounds__(512, 1) void sim_kernel() {
    extern __shared__ __nv_bfloat16 sm[];               // [A0][A1][B0][B1] = 61440 B
    __nv_bfloat16* As = sm;
    __nv_bfloat16* Bs = sm + 2 * APITCH;
    __shared__ float rownorm[256];
    __shared__ float colnorm[128];

    int tid = threadIdx.x, wid = tid >> 5, lane = tid & 31;
    int wr = wid >> 2, wc = wid & 3;                    // 4x4 warps of 64x32
    int b = blockIdx.z;
    int st = blockIdx.x >> 1, h = blockIdx.x & 1;
    int si = 0, rem = st;
    while (rem >= 8 - si) { rem -= (8 - si); ++si; }
    int sj = si + rem;
    int i0  = si * 256;
    int j0c = sj * 256 + h * 128;

    if (tid < 256) rownorm[tid] = (i0 + tid < NN) ? g_norm[b * NN + i0 + tid] : 0.f;
    if (tid < 128) colnorm[tid] = (j0c + tid < NN) ? g_norm[b * NN + j0c + tid] : 0.f;

    wmma::fragment<wmma::accumulator, 16, 16, 16, float> acc[4][2];
#pragma unroll
    for (int i = 0; i < 4; ++i)
#pragma unroll
        for (int j = 0; j < 2; ++j) wmma::fill_fragment(acc[i][j], 0.f);

    const __nv_bfloat16* xb = g_xb + (size_t)b * NN * CC;
    uint32_t sbase = (uint32_t)__cvta_generic_to_shared(sm);

    // cp.async stage fill: 1536 x 16B chunks (A 1024, B 512), 3 per thread
    auto fill = [&](int sg, int kb) {
        int k0 = kb * SBK;
#pragma unroll
        for (int i = 0; i < 3; ++i) {
            int idx = tid + i * 512;
            bool isA = idx < 1024;
            int id2 = isA ? idx : idx - 1024;
            int row = id2 >> 2, ch = id2 & 3;
            int grow = (isA ? i0 : j0c) + row;
            bool ok = grow < NN;
            const void* src = xb + ((size_t)(ok ? grow : 0) * CC + k0 + ch * 8);
            uint32_t dst = sbase + (isA ? sg * ABYTES : 2 * ABYTES + sg * BBYTES)
                         + row * (SLD * 2) + ch * 16;
            cp_async16(dst, src, ok ? 16 : 0);
        }
        CP_COMMIT();
    };

    fill(0, 0);
    fill(1, 1);

    for (int kb = 0; kb < NKB; ++kb) {
        int cur = kb & 1;
        CP_WAIT1();
        __syncthreads();
        const __nv_bfloat16* Ac = As + cur * APITCH;
        const __nv_bfloat16* Bc = Bs + cur * BPITCH;
#pragma unroll
        for (int kf = 0; kf < 2; ++kf) {
            wmma::fragment<wmma::matrix_a, 16, 16, 16, __nv_bfloat16, wmma::row_major> af[4];
#pragma unroll
            for (int i = 0; i < 4; ++i)
                wmma::load_matrix_sync(af[i], Ac + (wr * 64 + i * 16) * SLD + kf * 16, SLD);
#pragma unroll
            for (int j = 0; j < 2; ++j) {
                wmma::fragment<wmma::matrix_b, 16, 16, 16, __nv_bfloat16, wmma::col_major> bf;
                wmma::load_matrix_sync(bf, Bc + (wc * 32 + j * 16) * SLD + kf * 16, SLD);
#pragma unroll
                for (int i = 0; i < 4; ++i)
                    wmma::mma_sync(acc[i][j], af[i], bf, acc[i][j]);
            }
        }
        __syncthreads();
        if (kb + 2 < NKB) fill(cur, kb + 2);
        else CP_COMMIT();                               // keep group count invariant
    }

    // epilogue: threshold + bit words, both orientations. Reuse smem as stage.
    float* stage = (float*)sm + wid * (16 * STGLD);     // 16x36 floats per warp (36KB)
    int colbase = wc * 32;
    int col = j0c + colbase + lane;
    bool colok = col < NN;
    float nj = colnorm[colbase + lane];
    unsigned mw0 = 0, mw1 = 0;
#pragma unroll
    for (int i = 0; i < 4; ++i) {
        wmma::store_matrix_sync(stage,      acc[i][0], STGLD, wmma::mem_row_major);
        wmma::store_matrix_sync(stage + 16, acc[i][1], STGLD, wmma::mem_row_major);
        __syncwarp();
        for (int rr = 0; rr < 16; ++rr) {
            int lr = wr * 64 + i * 16 + rr;             // local row 0..255
            int row = i0 + lr;
            bool rowok = row < NN;
            float ni = rownorm[lr];
            float val = stage[rr * STGLD + lane];
            bool pred = rowok && colok && (val >= 0.5f * ni * nj);
            unsigned word = __ballot_sync(0xFFFFFFFFu, pred);
            if (lane == 0 && rowok)
                g_Asim[((size_t)b * NN + row) * NWRD + ((j0c + colbase) >> 5)] = word;
            int lrr = i * 16 + rr;                      // 0..63 within warp rows
            if (lrr < 32) mw0 |= (pred ? 1u : 0u) << lrr;
            else          mw1 |= (pred ? 1u : 0u) << (lrr - 32);
        }
        __syncwarp();
    }
    if (colok) {
        size_t base = ((size_t)b * NN + col) * NWRD + ((i0 + wr * 64) >> 5);
        g_Asim[base]     = mw0;
        g_Asim[base + 1] = mw1;
    }
}

// ---------------- 4) Z = (x @ [W1c|W1d]) * inv_s (bf16 split, double-buffered) ----------------
#define ZM 128
#define ZN 96
#define ZK 32
#define ZLDA 40                      // 32 + 8 pad (halves)
#define ZLDB 104                     // 96 + 8 pad
#define ZAP (ZM * ZLDA)              // A stage pitch (elems) = 5120
#define ZWP (ZK * ZLDB)              // W stage pitch (elems) = 3328

__global__ void __launch_bounds__(384, 1) z_kernel_tc() {
    extern __shared__ __nv_bfloat16 zsm[];
    __nv_bfloat16* Ah = zsm;                     // 2 * ZAP
    __nv_bfloat16* Al = zsm + 2 * ZAP;           // 2 * ZAP
    __nv_bfloat16* Wh = zsm + 4 * ZAP;           // 2 * ZWP
    __nv_bfloat16* Wl = zsm + 4 * ZAP + 2 * ZWP; // 2 * ZWP

    int tid = threadIdx.x;
    int wid = tid >> 5, lane = tid & 31;
    int wr = wid / 3, wc = wid % 3;              // 4 x 3 warps, 32x32 tiles
    int row0 = blockIdx.x * ZM;                  // 125 blocks cover 16000 rows exactly

    wmma::fragment<wmma::accumulator, 16, 16, 16, float> acc[2][2];
#pragma unroll
    for (int i = 0; i < 2; ++i)
#pragma unroll
        for (int j = 0; j < 2; ++j) wmma::fill_fragment(acc[i][j], 0.f);

    // staging registers: A 512 uint4 (hi+lo), W 384 uint4 (hi+lo)
    uint4 rah[2], ral[2], rwh, rwl;
    {
#pragma unroll
        for (int i = 0; i < 2; ++i) {
            int idx = tid + i * 384;
            if (idx < 512) {
                int row = idx >> 2, ch = idx & 3;
                size_t off = (size_t)(row0 + row) * CC + ch * 8;
                rah[i] = *(const uint4*)(g_xb + off);
                ral[i] = *(const uint4*)(g_xl + off);
            }
        }
        {
            int row = tid / 12, cs = tid % 12;
            size_t off = (size_t)row * ZN + cs * 8;
            rwh = *(const uint4*)(g_Wh + off);
            rwl = *(const uint4*)(g_Wl + off);
        }
#pragma unroll
        for (int i = 0; i < 2; ++i) {
            int idx = tid + i * 384;
            if (idx < 512) {
                int row = idx >> 2, ch = idx & 3;
                *(uint4*)&Ah[row * ZLDA + ch * 8] = rah[i];
                *(uint4*)&Al[row * ZLDA + ch * 8] = ral[i];
            }
        }
        {
            int row = tid / 12, cs = tid % 12;
            *(uint4*)&Wh[row * ZLDB + cs * 8] = rwh;
            *(uint4*)&Wl[row * ZLDB + cs * 8] = rwl;
        }
    }
    __syncthreads();

    for (int kb = 0; kb < CC / ZK; ++kb) {
        int cur = kb & 1, nxt = cur ^ 1;
        bool more = kb + 1 < CC / ZK;
        if (more) {
            int k0 = (kb + 1) * ZK;
#pragma unroll
            for (int i = 0; i < 2; ++i) {
                int idx = tid + i * 384;
                if (idx < 512) {
                    int row = idx >> 2, ch = idx & 3;
                    size_t off = (size_t)(row0 + row) * CC + k0 + ch * 8;
                    rah[i] = *(const uint4*)(g_xb + off);
                    ral[i] = *(const uint4*)(g_xl + off);
                }
            }
            {
                int row = tid / 12, cs = tid % 12;
                size_t off = (size_t)(k0 + row) * ZN + cs * 8;
                rwh = *(const uint4*)(g_Wh + off);
                rwl = *(const uint4*)(g_Wl + off);
            }
        }
        const __nv_bfloat16* Ahc = Ah + cur * ZAP;
        const __nv_bfloat16* Alc = Al + cur * ZAP;
        const __nv_bfloat16* Whc = Wh + cur * ZWP;
        const __nv_bfloat16* Wlc = Wl + cur * ZWP;
#pragma unroll
        for (int ks = 0; ks < 2; ++ks) {
            wmma::fragment<wmma::matrix_a, 16, 16, 16, __nv_bfloat16, wmma::row_major> ah[2], al[2];
            wmma::fragment<wmma::matrix_b, 16, 16, 16, __nv_bfloat16, wmma::row_major> bh[2], bl[2];
#pragma unroll
            for (int i = 0; i < 2; ++i) {
                wmma::load_matrix_sync(ah[i], Ahc + (wr * 32 + i * 16) * ZLDA + ks * 16, ZLDA);
                wmma::load_matrix_sync(al[i], Alc + (wr * 32 + i * 16) * ZLDA + ks * 16, ZLDA);
            }
#pragma unroll
            for (int j = 0; j < 2; ++j) {
                wmma::load_matrix_sync(bh[j], Whc + (ks * 16) * ZLDB + wc * 32 + j * 16, ZLDB);
                wmma::load_matrix_sync(bl[j], Wlc + (ks * 16) * ZLDB + wc * 32 + j * 16, ZLDB);
            }
#pragma unroll
            for (int i = 0; i < 2; ++i)
#pragma unroll
                for (int j = 0; j < 2; ++j) {
                    wmma::mma_sync(acc[i][j], ah[i], bh[j], acc[i][j]);
                    wmma::mma_sync(acc[i][j], ah[i], bl[j], acc[i][j]);
                    wmma::mma_sync(acc[i][j], al[i], bh[j], acc[i][j]);
                }
        }
        if (more) {
#pragma unroll
            for (int i = 0; i < 2; ++i) {
                int idx = tid + i * 384;
                if (idx < 512) {
                    int row = idx >> 2, ch = idx & 3;
                    *(uint4*)&Ah[nxt * ZAP + row * ZLDA + ch * 8] = rah[i];
                    *(uint4*)&Al[nxt * ZAP + row * ZLDA + ch * 8] = ral[i];
                }
            }
            {
                int row = tid / 12, cs = tid % 12;
                *(uint4*)&Wh[nxt * ZWP + row * ZLDB + cs * 8] = rwh;
                *(uint4*)&Wl[nxt * ZWP + row * ZLDB + cs * 8] = rwl;
            }
        }
        __syncthreads();
    }

    // epilogue: stage per warp (alias onto zsm), scale by inv_s, write cols < 84
    float* ws = (float*)zsm + wid * 256;
#pragma unroll
    for (int i = 0; i < 2; ++i)
#pragma unroll
        for (int j = 0; j < 2; ++j) {
            wmma::store_matrix_sync(ws, acc[i][j], 16, wmma::mem_row_major);
            __syncwarp();
            int grow0 = row0 + wr * 32 + i * 16;
            int gcol0 = wc * 32 + j * 16;
            for (int e = lane; e < 256; e += 32) {
                int rr = e >> 4, cc = e & 15;
                int gc = gcol0 + cc;
                if (gc < F2) {
                    int gr = grow0 + rr;
                    g_Z[(size_t)gr * F2 + gc] = ws[e] * g_inv_s[gr];
                }
            }
            __syncwarp();
        }
}

// ---------------- 5) H = relu(A @ Z + b1) ----------------
__global__ void agg1_kernel(const float* __restrict__ b1c, const float* __restrict__ b1d) {
    int i = blockIdx.x, br = blockIdx.y, b = blockIdx.z;
    __shared__ unsigned wds[NWRD];
    int t = threadIdx.x;                                 // 64
    const unsigned* A = (br ? g_Asim : g_Aadj) + ((size_t)b * NN + i) * NWRD;
    if (t < NWRD) wds[t] = A[t];
    __syncthreads();
    if (t >= HID) return;
    float acc = 0.f;
    const float* Zb = g_Z + (size_t)b * NN * F2 + br * HID;
    for (int w = 0; w < NWRD; ++w) {
        unsigned m = wds[w];
        while (m) {
            int j = w * 32 + __ffs(m) - 1;
            m &= m - 1;
            acc += Zb[(size_t)j * F2 + t];
        }
    }
    float bias = br ? b1d[t] : b1c[t];
    g_H[((size_t)b * NN + i) * F2 + br * HID + t] = fmaxf(acc + bias, 0.f);
}

// ---------------- 6) T = H @ [W_cls2 | W_det2] ----------------
__global__ void t_kernel(const float* __restrict__ W2c, const float* __restrict__ W2d) {
    int g = blockIdx.x * blockDim.x + threadIdx.x;
    if (g >= BB * NN * 40) return;
    int c40 = g % 40; int i = g / 40;
    int br = c40 / 20, c = c40 % 20;
    const float* W = br ? W2d : W2c;
    const float* h = g_H + (size_t)i * F2 + br * HID;
    float acc = 0.f;
#pragma unroll
    for (int f = 0; f < HID; ++f) acc += h[f] * W[f * NCLS + c];
    g_T[(size_t)i * 40 + c40] = acc;
}

// ---------------- 7) out = A @ T + b2, cls branch: fused class softmax ----------------
__global__ void agg2_kernel(const float* __restrict__ b2c, const float* __restrict__ b2d,
                            float* __restrict__ out) {
    int i = blockIdx.x, br = blockIdx.y, b = blockIdx.z;
    __shared__ unsigned wds[NWRD];
    int t = threadIdx.x;                                 // 32
    const unsigned* A = (br ? g_Asim : g_Aadj) + ((size_t)b * NN + i) * NWRD;
    wds[t] = A[t]; wds[t + 32] = A[t + 32];
    __syncthreads();
    bool act = t < NCLS;
    float acc = 0.f;
    if (act) {
        const float* Tb = g_T + (size_t)b * NN * 40 + br * NCLS;
        for (int w = 0; w < NWRD; ++w) {
            unsigned m = wds[w];
            while (m) {
                int j = w * 32 + __ffs(m) - 1;
                m &= m - 1;
                acc += Tb[(size_t)j * 40 + t];
            }
        }
        acc += br ? b2d[t] : b2c[t];
    }
    if (br == 0) {
        float v = act ? acc : -1e30f;
        float mx = v;
#pragma unroll
        for (int off = 16; off > 0; off >>= 1)
            mx = fmaxf(mx, __shfl_xor_sync(0xFFFFFFFFu, mx, off));
        float e = act ? expf(v - mx) : 0.f;
        float s = e;
#pragma unroll
        for (int off = 16; off > 0; off >>= 1)
            s += __shfl_xor_sync(0xFFFFFFFFu, s, off);
        acc = e / s;
    }
    if (act)
        out[(size_t)br * BB * NN * NCLS + ((size_t)b * NN + i) * NCLS + t] = acc;
}

// ---------------- 8) softmax over proposals (det half, per (b, class)) ----------------
__global__ void softmax_det(float* __restrict__ out) {
    int b = blockIdx.x / NCLS, c = blockIdx.x % NCLS;
    float* p = out + (size_t)BB * NN * NCLS + (size_t)b * NN * NCLS + c;
    __shared__ float buf[NN];
    __shared__ float red[256];
    int t = threadIdx.x;
    float mx = -1e30f;
    for (int j = t; j < NN; j += 256) {
        float v = p[(size_t)j * NCLS];
        buf[j] = v;
        mx = fmaxf(mx, v);
    }
    red[t] = mx; __syncthreads();
    for (int off = 128; off > 0; off >>= 1) {
        if (t < off) red[t] = fmaxf(red[t], red[t + off]);
        __syncthreads();
    }
    mx = red[0];
    __syncthreads();
    float s = 0.f;
    for (int j = t; j < NN; j += 256) {
        float e = expf(buf[j] - mx);
        buf[j] = e;
        s += e;
    }
    red[t] = s; __syncthreads();
    for (int off = 128; off > 0; off >>= 1) {
        if (t < off) red[t] += red[t + off];
        __syncthreads();
    }
    float inv = 1.f / red[0];
    for (int j = t; j < NN; j += 256) p[(size_t)j * NCLS] = buf[j] * inv;
}

// ---------------- launcher ----------------
extern "C" void kernel_launch(void* const* d_in, const int* in_sizes, int n_in,
                              void* d_out, int out_size) {
    const float* x1    = (const float*)d_in[0];
    const float* boxes = (const float*)d_in[2];
    const float* Wc1   = (const float*)d_in[3];
    const float* bc1   = (const float*)d_in[4];
    const float* Wc2   = (const float*)d_in[5];
    const float* bc2   = (const float*)d_in[6];
    const float* Wd1   = (const float*)d_in[7];
    const float* bd1   = (const float*)d_in[8];
    const float* Wd2   = (const float*)d_in[9];
    const float* bd2   = (const float*)d_in[10];
    float* out = (float*)d_out;

    const int simSmem = 2 * (ABYTES + BBYTES);                                   // 61440
    cudaFuncSetAttribute(sim_kernel, cudaFuncAttributeMaxDynamicSharedMemorySize, simSmem);
    const int zSmem = (4 * ZAP + 4 * ZWP) * (int)sizeof(__nv_bfloat16);          // 67584
    cudaFuncSetAttribute(z_kernel_tc, cudaFuncAttributeMaxDynamicSharedMemorySize, zSmem);

    prep_kernel<<<BB * NN, 128>>>(x1);
    wprep_kernel<<<(4096 * 96 + 255) / 256, 256>>>(Wc1, Wd1);
    iou_kernel<<<dim3(NN / 4, BB), 256>>>(boxes);
    sim_kernel<<<dim3(72, 1, BB), 512, simSmem>>>();
    z_kernel_tc<<<(BB * NN) / ZM, 384, zSmem>>>();
    agg1_kernel<<<dim3(NN, 2, BB), 64>>>(bc1, bd1);
    t_kernel<<<(BB * NN * 40 + 255) / 256, 256>>>(Wc2, Wd2);
    agg2_kernel<<<dim3(NN, 2, BB), 32>>>(bc2, bd2, out);
    softmax_det<<<BB * NCLS, 256>>>(out);
}

// round 15
// speedup vs baseline: 2.2738x; 1.0678x over previous
#include <cuda_runtime.h>
#include <cuda_bf16.h>
#include <mma.h>
#include <cstdint>

using namespace nvcuda;

#define BB   8
#define NN   2000
#define CC   4096
#define HID  42
#define NCLS 20
#define NWRD 64          // 64 * 32 = 2048 bits >= 2000
#define F2   84          // 2*HID
#define THRESHF 0.5f
#define EPSF 1e-12f

// ---------------- scratch (device globals: allocation-free) ----------------
__device__ __nv_bfloat16 g_xb[(size_t)BB * NN * CC];     // bf16 hi of x1
__device__ __nv_bfloat16 g_xl[(size_t)BB * NN * CC];     // bf16 lo residual of x1
__device__ float    g_inv_s[BB * NN];                    // 1/rowsum (0 if sum==0)
__device__ float    g_norm[BB * NN];                     // max(||x_i||, EPS)
__device__ unsigned g_Aadj[(size_t)BB * NN * NWRD];      // IoU adjacency bitmask
__device__ unsigned g_Asim[(size_t)BB * NN * NWRD];      // cosine-sim adjacency bitmask
__device__ float    g_Z[(size_t)BB * NN * F2];           // (x @ [W_cls1|W_det1]) * inv_s
__device__ float    g_H[(size_t)BB * NN * F2];           // relu(A @ Z + b1)
__device__ float    g_T[(size_t)BB * NN * 40];           // H @ [W_cls2 | W_det2]
__device__ __nv_bfloat16 g_Wh[4096 * 96];                // [W_cls1|W_det1|0pad] hi
__device__ __nv_bfloat16 g_Wl[4096 * 96];                // lo

// ---------------- cp.async helpers ----------------
__device__ __forceinline__ void cp_async16(uint32_t dst, const void* src, int srcsize) {
    asm volatile("cp.async.cg.shared.global [%0], [%1], 16, %2;"
                 :: "r"(dst), "l"(src), "r"(srcsize) : "memory");
}
#define CP_COMMIT() asm volatile("cp.async.commit_group;" ::: "memory")
#define CP_WAIT1()  asm volatile("cp.async.wait_group 1;" ::: "memory")

// ---------------- 1) row stats + bf16 hi/lo convert ----------------
__global__ void prep_kernel(const float* __restrict__ x) {
    int row = blockIdx.x;
    const float4* p = (const float4*)(x + (size_t)row * CC);
    __nv_bfloat162* q  = (__nv_bfloat162*)(g_xb + (size_t)row * CC);
    __nv_bfloat162* ql = (__nv_bfloat162*)(g_xl + (size_t)row * CC);
    int t = threadIdx.x;                                // 128
    float s = 0.f, sq = 0.f;
#pragma unroll
    for (int it = 0; it < (CC / 4) / 128; ++it) {
        int i4 = t + it * 128;
        float4 v = p[i4];
        s  += v.x + v.y + v.z + v.w;
        sq += v.x * v.x + v.y * v.y + v.z * v.z + v.w * v.w;
        __nv_bfloat162 h0 = __floats2bfloat162_rn(v.x, v.y);
        __nv_bfloat162 h1 = __floats2bfloat162_rn(v.z, v.w);
        q[i4 * 2]     = h0;
        q[i4 * 2 + 1] = h1;
        __nv_bfloat162 l0 = __floats2bfloat162_rn(v.x - __bfloat162float(h0.x),
                                                  v.y - __bfloat162float(h0.y));
        __nv_bfloat162 l1 = __floats2bfloat162_rn(v.z - __bfloat162float(h1.x),
                                                  v.w - __bfloat162float(h1.y));
        ql[i4 * 2]     = l0;
        ql[i4 * 2 + 1] = l1;
    }
    __shared__ float ss[128], sqq[128];
    ss[t] = s; sqq[t] = sq;
    __syncthreads();
    for (int off = 64; off > 0; off >>= 1) {
        if (t < off) { ss[t] += ss[t + off]; sqq[t] += sqq[t + off]; }
        __syncthreads();
    }
    if (t == 0) {
        float sum = ss[0];
        g_inv_s[row] = (sum == 0.f) ? 0.f : (1.f / sum);
        g_norm[row]  = fmaxf(sqrtf(sqq[0]), EPSF);
    }
}

// ---------------- 1b) weight hi/lo prep ----------------
__global__ void wprep_kernel(const float* __restrict__ Wc, const float* __restrict__ Wd) {
    int idx = blockIdx.x * blockDim.x + threadIdx.x;
    if (idx >= 4096 * 96) return;
    int k = idx / 96, c = idx % 96;
    float v = 0.f;
    if (c < HID)      v = Wc[k * HID + c];
    else if (c < F2)  v = Wd[k * HID + c - HID];
    __nv_bfloat16 h = __float2bfloat16(v);
    g_Wh[idx] = h;
    g_Wl[idx] = __float2bfloat16(v - __bfloat162float(h));
}

// ---------------- 2) pairwise IoU -> A_adj bitmask ----------------
__global__ void iou_kernel(const float* __restrict__ boxes) {
    int b = blockIdx.y;
    __shared__ float4 bx[NN];
    int t = threadIdx.x;                                // 256
    const float4* src = (const float4*)boxes + (size_t)b * NN;
    for (int idx = t; idx < NN; idx += 256) bx[idx] = src[idx];
    __syncthreads();

    int i = blockIdx.x * 4 + (t >> 6);
    int w = t & 63;
    float4 bi = bx[i];
    float ai = __fmul_rn(__fsub_rn(bi.z, bi.x), __fsub_rn(bi.w, bi.y));
    unsigned word = 0;
#pragma unroll 4
    for (int k = 0; k < 32; ++k) {
        int j = w * 32 + k;
        if (j < NN) {
            float4 bj = bx[j];
            float aj  = __fmul_rn(__fsub_rn(bj.z, bj.x), __fsub_rn(bj.w, bj.y));
            float ltx = fmaxf(bi.x, bj.x), lty = fmaxf(bi.y, bj.y);
            float rbx = fminf(bi.z, bj.z), rby = fminf(bi.w, bj.w);
            float wx  = fmaxf(__fsub_rn(rbx, ltx), 0.f);
            float wy  = fmaxf(__fsub_rn(rby, lty), 0.f);
            float inter = __fmul_rn(wx, wy);
            float uni   = __fsub_rn(__fadd_rn(ai, aj), inter);
            float iou   = inter / fmaxf(uni, EPSF);
            if (iou >= THRESHF) word |= (1u << k);
        }
    }
    g_Aadj[((size_t)b * NN + i) * NWRD + w] = word;
}

// ---------------- 3) sim: G = x x^T, 512 thr, 256x128 block / 64x32 warp tile ----------------
// grid.x = 72 (36 upper-tri 256x256 supertiles * 2 col-halves), grid.z = images
// SBK=64: 64 barrier pairs total; fragment loads hoisted per kf for ILP.
#define SBK 64
#define SLD 72                       // 64 + 8 halves: 144B pitch, conflict-free ldsm
#define APITCH (256 * SLD)           // elems
#define BPITCH (128 * SLD)
#define ABYTES (256 * SLD * 2)       // 36864
#define BBYTES (128 * SLD * 2)       // 18432
#define STGLD 36
#define NKB (CC / SBK)               // 64

__global__ __launch_bounds__(512, 1) void sim_kernel() {
    extern __shared__ __nv_bfloat16 sm[];               // [A0][A1][B0][B1] = 110592 B
    __nv_bfloat16* As = sm;
    __nv_bfloat16* Bs = sm + 2 * APITCH;
    __shared__ float rownorm[256];
    __shared__ float colnorm[128];

    int tid = threadIdx.x, wid = tid >> 5, lane = tid & 31;
    int wr = wid >> 2, wc = wid & 3;                    // 4x4 warps of 64x32
    int b = blockIdx.z;
    int st = blockIdx.x >> 1, h = blockIdx.x & 1;
    int si = 0, rem = st;
    while (rem >= 8 - si) { rem -= (8 - si); ++si; }
    int sj = si + rem;
    int i0  = si * 256;
    int j0c = sj * 256 + h * 128;

    if (tid < 256) rownorm[tid] = (i0 + tid < NN) ? g_norm[b * NN + i0 + tid] : 0.f;
    if (tid < 128) colnorm[tid] = (j0c + tid < NN) ? g_norm[b * NN + j0c + tid] : 0.f;

    wmma::fragment<wmma::accumulator, 16, 16, 16, float> acc[4][2];
#pragma unroll
    for (int i = 0; i < 4; ++i)
#pragma unroll
        for (int j = 0; j < 2; ++j) wmma::fill_fragment(acc[i][j], 0.f);

    const __nv_bfloat16* xb = g_xb + (size_t)b * NN * CC;
    uint32_t sbase = (uint32_t)__cvta_generic_to_shared(sm);

    // stage fill: (256 + 128) rows x 8 chunks of 16B = 3072 chunks, 6 per thread
    auto fill = [&](int sg, int kb) {
        int k0 = kb * SBK;
#pragma unroll
        for (int i = 0; i < 6; ++i) {
            int idx = tid + i * 512;
            bool isA = idx < 2048;
            int id2 = isA ? idx : idx - 2048;
            int row = id2 >> 3, ch = id2 & 7;
            int grow = (isA ? i0 : j0c) + row;
            bool ok = grow < NN;
            const void* src = xb + ((size_t)(ok ? grow : 0) * CC + k0 + ch * 8);
            uint32_t dst = sbase + (isA ? sg * ABYTES : 2 * ABYTES + sg * BBYTES)
                         + row * (SLD * 2) + ch * 16;
            cp_async16(dst, src, ok ? 16 : 0);
        }
        CP_COMMIT();
    };

    fill(0, 0);
    fill(1, 1);

    for (int kb = 0; kb < NKB; ++kb) {
        int cur = kb & 1;
        CP_WAIT1();
        __syncthreads();
        const __nv_bfloat16* Ac = As + cur * APITCH + (wr * 64) * SLD;
        const __nv_bfloat16* Bc = Bs + cur * BPITCH + (wc * 32) * SLD;
#pragma unroll
        for (int kf = 0; kf < 4; ++kf) {
            wmma::fragment<wmma::matrix_b, 16, 16, 16, __nv_bfloat16, wmma::col_major> bf[2];
#pragma unroll
            for (int j = 0; j < 2; ++j)
                wmma::load_matrix_sync(bf[j], Bc + (j * 16) * SLD + kf * 16, SLD);
            wmma::fragment<wmma::matrix_a, 16, 16, 16, __nv_bfloat16, wmma::row_major> af[4];
#pragma unroll
            for (int i = 0; i < 4; ++i)
                wmma::load_matrix_sync(af[i], Ac + (i * 16) * SLD + kf * 16, SLD);
#pragma unroll
            for (int i = 0; i < 4; ++i)
#pragma unroll
                for (int j = 0; j < 2; ++j)
                    wmma::mma_sync(acc[i][j], af[i], bf[j], acc[i][j]);
        }
        __syncthreads();
        if (kb + 2 < NKB) fill(cur, kb + 2);
        else CP_COMMIT();                               // keep group count invariant
    }

    // epilogue: threshold + bit words, both orientations. Reuse smem as stage.
    float* stage = (float*)sm + wid * (16 * STGLD);     // 16x36 floats per warp (36KB)
    int colbase = wc * 32;
    int col = j0c + colbase + lane;
    bool colok = col < NN;
    float nj = colnorm[colbase + lane];
    unsigned mw0 = 0, mw1 = 0;
#pragma unroll
    for (int i = 0; i < 4; ++i) {
        wmma::store_matrix_sync(stage,      acc[i][0], STGLD, wmma::mem_row_major);
        wmma::store_matrix_sync(stage + 16, acc[i][1], STGLD, wmma::mem_row_major);
        __syncwarp();
        for (int rr = 0; rr < 16; ++rr) {
            int lr = wr * 64 + i * 16 + rr;             // local row 0..255
            int row = i0 + lr;
            bool rowok = row < NN;
            float ni = rownorm[lr];
            float val = stage[rr * STGLD + lane];
            bool pred = rowok && colok && (val >= 0.5f * ni * nj);
            unsigned word = __ballot_sync(0xFFFFFFFFu, pred);
            if (lane == 0 && rowok)
                g_Asim[((size_t)b * NN + row) * NWRD + ((j0c + colbase) >> 5)] = word;
            int lrr = i * 16 + rr;                      // 0..63 within warp rows
            if (lrr < 32) mw0 |= (pred ? 1u : 0u) << lrr;
            else          mw1 |= (pred ? 1u : 0u) << (lrr - 32);
        }
        __syncwarp();
    }
    if (colok) {
        size_t base = ((size_t)b * NN + col) * NWRD + ((i0 + wr * 64) >> 5);
        g_Asim[base]     = mw0;
        g_Asim[base + 1] = mw1;
    }
}

// ---------------- 4) Z = (x @ [W1c|W1d]) * inv_s (bf16 split, double-buffered) ----------------
#define ZM 128
#define ZN 96
#define ZK 32
#define ZLDA 40                      // 32 + 8 pad (halves)
#define ZLDB 104                     // 96 + 8 pad
#define ZAP (ZM * ZLDA)              // A stage pitch (elems) = 5120
#define ZWP (ZK * ZLDB)              // W stage pitch (elems) = 3328

__global__ void __launch_bounds__(384, 1) z_kernel_tc() {
    extern __shared__ __nv_bfloat16 zsm[];
    __nv_bfloat16* Ah = zsm;                     // 2 * ZAP
    __nv_bfloat16* Al = zsm + 2 * ZAP;           // 2 * ZAP
    __nv_bfloat16* Wh = zsm + 4 * ZAP;           // 2 * ZWP
    __nv_bfloat16* Wl = zsm + 4 * ZAP + 2 * ZWP; // 2 * ZWP

    int tid = threadIdx.x;
    int wid = tid >> 5, lane = tid & 31;
    int wr = wid / 3, wc = wid % 3;              // 4 x 3 warps, 32x32 tiles
    int row0 = blockIdx.x * ZM;                  // 125 blocks cover 16000 rows exactly

    wmma::fragment<wmma::accumulator, 16, 16, 16, float> acc[2][2];
#pragma unroll
    for (int i = 0; i < 2; ++i)
#pragma unroll
        for (int j = 0; j < 2; ++j) wmma::fill_fragment(acc[i][j], 0.f);

    // staging registers: A 512 uint4 (hi+lo), W 384 uint4 (hi+lo)
    uint4 rah[2], ral[2], rwh, rwl;
    {
#pragma unroll
        for (int i = 0; i < 2; ++i) {
            int idx = tid + i * 384;
            if (idx < 512) {
                int row = idx >> 2, ch = idx & 3;
                size_t off = (size_t)(row0 + row) * CC + ch * 8;
                rah[i] = *(const uint4*)(g_xb + off);
                ral[i] = *(const uint4*)(g_xl + off);
            }
        }
        {
            int row = tid / 12, cs = tid % 12;
            size_t off = (size_t)row * ZN + cs * 8;
            rwh = *(const uint4*)(g_Wh + off);
            rwl = *(const uint4*)(g_Wl + off);
        }
#pragma unroll
        for (int i = 0; i < 2; ++i) {
            int idx = tid + i * 384;
            if (idx < 512) {
                int row = idx >> 2, ch = idx & 3;
                *(uint4*)&Ah[row * ZLDA + ch * 8] = rah[i];
                *(uint4*)&Al[row * ZLDA + ch * 8] = ral[i];
            }
        }
        {
            int row = tid / 12, cs = tid % 12;
            *(uint4*)&Wh[row * ZLDB + cs * 8] = rwh;
            *(uint4*)&Wl[row * ZLDB + cs * 8] = rwl;
        }
    }
    __syncthreads();

    for (int kb = 0; kb < CC / ZK; ++kb) {
        int cur = kb & 1, nxt = cur ^ 1;
        bool more = kb + 1 < CC / ZK;
        if (more) {
            int k0 = (kb + 1) * ZK;
#pragma unroll
            for (int i = 0; i < 2; ++i) {
                int idx = tid + i * 384;
                if (idx < 512) {
                    int row = idx >> 2, ch = idx & 3;
                    size_t off = (size_t)(row0 + row) * CC + k0 + ch * 8;
                    rah[i] = *(const uint4*)(g_xb + off);
                    ral[i] = *(const uint4*)(g_xl + off);
                }
            }
            {
                int row = tid / 12, cs = tid % 12;
                size_t off = (size_t)(k0 + row) * ZN + cs * 8;
                rwh = *(const uint4*)(g_Wh + off);
                rwl = *(const uint4*)(g_Wl + off);
            }
        }
        const __nv_bfloat16* Ahc = Ah + cur * ZAP;
        const __nv_bfloat16* Alc = Al + cur * ZAP;
        const __nv_bfloat16* Whc = Wh + cur * ZWP;
        const __nv_bfloat16* Wlc = Wl + cur * ZWP;
#pragma unroll
        for (int ks = 0; ks < 2; ++ks) {
            wmma::fragment<wmma::matrix_a, 16, 16, 16, __nv_bfloat16, wmma::row_major> ah[2], al[2];
            wmma::fragment<wmma::matrix_b, 16, 16, 16, __nv_bfloat16, wmma::row_major> bh[2], bl[2];
#pragma unroll
            for (int i = 0; i < 2; ++i) {
                wmma::load_matrix_sync(ah[i], Ahc + (wr * 32 + i * 16) * ZLDA + ks * 16, ZLDA);
                wmma::load_matrix_sync(al[i], Alc + (wr * 32 + i * 16) * ZLDA + ks * 16, ZLDA);
            }
#pragma unroll
            for (int j = 0; j < 2; ++j) {
                wmma::load_matrix_sync(bh[j], Whc + (ks * 16) * ZLDB + wc * 32 + j * 16, ZLDB);
                wmma::load_matrix_sync(bl[j], Wlc + (ks * 16) * ZLDB + wc * 32 + j * 16, ZLDB);
            }
#pragma unroll
            for (int i = 0; i < 2; ++i)
#pragma unroll
                for (int j = 0; j < 2; ++j) {
                    wmma::mma_sync(acc[i][j], ah[i], bh[j], acc[i][j]);
                    wmma::mma_sync(acc[i][j], ah[i], bl[j], acc[i][j]);
                    wmma::mma_sync(acc[i][j], al[i], bh[j], acc[i][j]);
                }
        }
        if (more) {
#pragma unroll
            for (int i = 0; i < 2; ++i) {
                int idx = tid + i * 384;
                if (idx < 512) {
                    int row = idx >> 2, ch = idx & 3;
                    *(uint4*)&Ah[nxt * ZAP + row * ZLDA + ch * 8] = rah[i];
                    *(uint4*)&Al[nxt * ZAP + row * ZLDA + ch * 8] = ral[i];
                }
            }
            {
                int row = tid / 12, cs = tid % 12;
                *(uint4*)&Wh[nxt * ZWP + row * ZLDB + cs * 8] = rwh;
                *(uint4*)&Wl[nxt * ZWP + row * ZLDB + cs * 8] = rwl;
            }
        }
        __syncthreads();
    }

    // epilogue: stage per warp (alias onto zsm), scale by inv_s, write cols < 84
    float* ws = (float*)zsm + wid * 256;
#pragma unroll
    for (int i = 0; i < 2; ++i)
#pragma unroll
        for (int j = 0; j < 2; ++j) {
            wmma::store_matrix_sync(ws, acc[i][j], 16, wmma::mem_row_major);
            __syncwarp();
            int grow0 = row0 + wr * 32 + i * 16;
            int gcol0 = wc * 32 + j * 16;
            for (int e = lane; e < 256; e += 32) {
                int rr = e >> 4, cc = e & 15;
                int gc = gcol0 + cc;
                if (gc < F2) {
                    int gr = grow0 + rr;
                    g_Z[(size_t)gr * F2 + gc] = ws[e] * g_inv_s[gr];
                }
            }
            __syncwarp();
        }
}

// ---------------- 5) H = relu(A @ Z + b1) ----------------
__global__ void agg1_kernel(const float* __restrict__ b1c, const float* __restrict__ b1d) {
    int i = blockIdx.x, br = blockIdx.y, b = blockIdx.z;
    __shared__ unsigned wds[NWRD];
    int t = threadIdx.x;                                 // 64
    const unsigned* A = (br ? g_Asim : g_Aadj) + ((size_t)b * NN + i) * NWRD;
    if (t < NWRD) wds[t] = A[t];
    __syncthreads();
    if (t >= HID) return;
    float acc = 0.f;
    const float* Zb = g_Z + (size_t)b * NN * F2 + br * HID;
    for (int w = 0; w < NWRD; ++w) {
        unsigned m = wds[w];
        while (m) {
            int j = w * 32 + __ffs(m) - 1;
            m &= m - 1;
            acc += Zb[(size_t)j * F2 + t];
        }
    }
    float bias = br ? b1d[t] : b1c[t];
    g_H[((size_t)b * NN + i) * F2 + br * HID + t] = fmaxf(acc + bias, 0.f);
}

// ---------------- 6) T = H @ [W_cls2 | W_det2] ----------------
__global__ void t_kernel(const float* __restrict__ W2c, const float* __restrict__ W2d) {
    int g = blockIdx.x * blockDim.x + threadIdx.x;
    if (g >= BB * NN * 40) return;
    int c40 = g % 40; int i = g / 40;
    int br = c40 / 20, c = c40 % 20;
    const float* W = br ? W2d : W2c;
    const float* h = g_H + (size_t)i * F2 + br * HID;
    float acc = 0.f;
#pragma unroll
    for (int f = 0; f < HID; ++f) acc += h[f] * W[f * NCLS + c];
    g_T[(size_t)i * 40 + c40] = acc;
}

// ---------------- 7) out = A @ T + b2, cls branch: fused class softmax ----------------
__global__ void agg2_kernel(const float* __restrict__ b2c, const float* __restrict__ b2d,
                            float* __restrict__ out) {
    int i = blockIdx.x, br = blockIdx.y, b = blockIdx.z;
    __shared__ unsigned wds[NWRD];
    int t = threadIdx.x;                                 // 32
    const unsigned* A = (br ? g_Asim : g_Aadj) + ((size_t)b * NN + i) * NWRD;
    wds[t] = A[t]; wds[t + 32] = A[t + 32];
    __syncthreads();
    bool act = t < NCLS;
    float acc = 0.f;
    if (act) {
        const float* Tb = g_T + (size_t)b * NN * 40 + br * NCLS;
        for (int w = 0; w < NWRD; ++w) {
            unsigned m = wds[w];
            while (m) {
                int j = w * 32 + __ffs(m) - 1;
                m &= m - 1;
                acc += Tb[(size_t)j * 40 + t];
            }
        }
        acc += br ? b2d[t] : b2c[t];
    }
    if (br == 0) {
        float v = act ? acc : -1e30f;
        float mx = v;
#pragma unroll
        for (int off = 16; off > 0; off >>= 1)
            mx = fmaxf(mx, __shfl_xor_sync(0xFFFFFFFFu, mx, off));
        float e = act ? expf(v - mx) : 0.f;
        float s = e;
#pragma unroll
        for (int off = 16; off > 0; off >>= 1)
            s += __shfl_xor_sync(0xFFFFFFFFu, s, off);
        acc = e / s;
    }
    if (act)
        out[(size_t)br * BB * NN * NCLS + ((size_t)b * NN + i) * NCLS + t] = acc;
}

// ---------------- 8) softmax over proposals (det half, per (b, class)) ----------------
__global__ void softmax_det(float* __restrict__ out) {
    int b = blockIdx.x / NCLS, c = blockIdx.x % NCLS;
    float* p = out + (size_t)BB * NN * NCLS + (size_t)b * NN * NCLS + c;
    __shared__ float buf[NN];
    __shared__ float red[256];
    int t = threadIdx.x;
    float mx = -1e30f;
    for (int j = t; j < NN; j += 256) {
        float v = p[(size_t)j * NCLS];
        buf[j] = v;
        mx = fmaxf(mx, v);
    }
    red[t] = mx; __syncthreads();
    for (int off = 128; off > 0; off >>= 1) {
        if (t < off) red[t] = fmaxf(red[t], red[t + off]);
        __syncthreads();
    }
    mx = red[0];
    __syncthreads();
    float s = 0.f;
    for (int j = t; j < NN; j += 256) {
        float e = expf(buf[j] - mx);
        buf[j] = e;
        s += e;
    }
    red[t] = s; __syncthreads();
    for (int off = 128; off > 0; off >>= 1) {
        if (t < off) red[t] += red[t + off];
        __syncthreads();
    }
    float inv = 1.f / red[0];
    for (int j = t; j < NN; j += 256) p[(size_t)j * NCLS] = buf[j] * inv;
}

// ---------------- launcher ----------------
extern "C" void kernel_launch(void* const* d_in, const int* in_sizes, int n_in,
                              void* d_out, int out_size) {
    const float* x1    = (const float*)d_in[0];
    const float* boxes = (const float*)d_in[2];
    const float* Wc1   = (const float*)d_in[3];
    const float* bc1   = (const float*)d_in[4];
    const float* Wc2   = (const float*)d_in[5];
    const float* bc2   = (const float*)d_in[6];
    const float* Wd1   = (const float*)d_in[7];
    const float* bd1   = (const float*)d_in[8];
    const float* Wd2   = (const float*)d_in[9];
    const float* bd2   = (const float*)d_in[10];
    float* out = (float*)d_out;

    const int simSmem = 2 * (ABYTES + BBYTES);                                   // 110592
    cudaFuncSetAttribute(sim_kernel, cudaFuncAttributeMaxDynamicSharedMemorySize, simSmem);
    const int zSmem = (4 * ZAP + 4 * ZWP) * (int)sizeof(__nv_bfloat16);          // 67584
    cudaFuncSetAttribute(z_kernel_tc, cudaFuncAttributeMaxDynamicSharedMemorySize, zSmem);

    prep_kernel<<<BB * NN, 128>>>(x1);
    wprep_kernel<<<(4096 * 96 + 255) / 256, 256>>>(Wc1, Wd1);
    iou_kernel<<<dim3(NN / 4, BB), 256>>>(boxes);
    sim_kernel<<<dim3(72, 1, BB), 512, simSmem>>>();
    z_kernel_tc<<<(BB * NN) / ZM, 384, zSmem>>>();
    agg1_kernel<<<dim3(NN, 2, BB), 64>>>(bc1, bd1);
    t_kernel<<<(BB * NN * 40 + 255) / 256, 256>>>(Wc2, Wd2);
    agg2_kernel<<<dim3(NN, 2, BB), 32>>>(bc2, bd2, out);
    softmax_det<<<BB * NCLS, 256>>>(out);
}